// round 1
// baseline (speedup 1.0000x reference)
#include <cuda_runtime.h>
#include <math.h>

#define SQ   2048      // tokens
#define DM   768       // model dim
#define NH   12        // heads
#define HD   64        // head dim
#define NE   8         // experts
#define NI   1024      // expert inter dim
#define ISH  2048      // shared inter dim
#define NSLOT (2*SQ)   // token-slots (top-2)

// ---------------- device scratch (static, no runtime alloc) ----------------
__device__ __align__(16) float g_xn [SQ*DM];
__device__ __align__(16) float g_res[SQ*DM];
__device__ __align__(16) float g_xf [SQ*DM];
__device__ __align__(16) float g_t  [SQ*ISH];
__device__ __align__(16) float g_a  [NSLOT*NI];
__device__ __align__(16) float g_gv [NSLOT*NI];
__device__ __align__(16) float g_h  [NSLOT*NI];
__device__ __align__(16) float g_yk [NSLOT*DM];
__device__ int   g_idx[NSLOT];
__device__ float g_wts[NSLOT];
__device__ int   g_counts[NE];
__device__ int   g_offsets[NE];
__device__ int   g_fill[NE];
__device__ int   g_list[NSLOT];

// ---------------- rmsnorm ----------------
// WHICH=0: in = x (param), out = g_xn ;  WHICH=1: in = g_res, out = g_xf
template<int WHICH>
__global__ void __launch_bounds__(256) rmsnorm_kernel(const float* __restrict__ x,
                                                      const float* __restrict__ w)
{
    int n = blockIdx.x;
    const float* row = (WHICH == 0) ? (x + (size_t)n*DM) : (g_res + (size_t)n*DM);
    float* out = (WHICH == 0) ? (g_xn + (size_t)n*DM) : (g_xf + (size_t)n*DM);

    float ss = 0.f;
    for (int d = threadIdx.x; d < DM; d += 256) { float v = row[d]; ss += v*v; }

    __shared__ float red[8];
    #pragma unroll
    for (int o = 16; o; o >>= 1) ss += __shfl_down_sync(0xffffffffu, ss, o);
    if ((threadIdx.x & 31) == 0) red[threadIdx.x >> 5] = ss;
    __syncthreads();
    if (threadIdx.x < 8) {
        ss = red[threadIdx.x];
        #pragma unroll
        for (int o = 4; o; o >>= 1) ss += __shfl_down_sync(0xffu, ss, o);
        if (threadIdx.x == 0) red[0] = ss;
    }
    __syncthreads();
    float inv = rsqrtf(red[0] * (1.0f/DM) + 1e-5f);
    for (int d = threadIdx.x; d < DM; d += 256) out[d] = row[d] * inv * w[d];
}

// ---------------- attention (flash-style, no max-subtract) ----------------
// q = k = v = g_xn head slice. writes g_res = x + attn_out
__global__ void __launch_bounds__(256) attn_kernel(const float* __restrict__ x)
{
    int q0 = blockIdx.x * 32;
    int h  = blockIdx.y;

    __shared__ __align__(16) float Qs[32][68];
    __shared__ __align__(16) float Ks[64][68];
    __shared__ __align__(16) float Ps[32][68];
    __shared__ float rs[32];

    int tid = threadIdx.x;
    int tx = tid & 15, ty = tid >> 4;

    // load Q tile (32 x 64)
    {
        int r = tid >> 3;           // 0..31
        int c = (tid & 7) * 8;      // 0..56
        const float* src = g_xn + (size_t)(q0 + r)*DM + h*HD + c;
        *(float4*)&Qs[r][c]     = *(const float4*)src;
        *(float4*)&Qs[r][c + 4] = *(const float4*)(src + 4);
    }

    float o[2][4] = {};
    float rsum = 0.f;

    for (int kt = 0; kt < SQ/64; kt++) {
        int k0 = kt * 64;
        __syncthreads();   // Ks/Ps consumers of prev tile done; Q ready on first iter
        {
            int r = tid >> 2;            // 0..63
            int c = (tid & 3) * 16;
            const float* src = g_xn + (size_t)(k0 + r)*DM + h*HD + c;
            #pragma unroll
            for (int v = 0; v < 4; v++)
                *(float4*)&Ks[r][c + v*4] = *(const float4*)(src + v*4);
        }
        __syncthreads();

        // S = Q K^T * (1/8), P = exp(S)
        float s[2][4] = {};
        #pragma unroll
        for (int d = 0; d < HD; d += 4) {
            float4 a0 = *(const float4*)&Qs[ty][d];
            float4 a1 = *(const float4*)&Qs[ty + 16][d];
            #pragma unroll
            for (int j = 0; j < 4; j++) {
                float4 b = *(const float4*)&Ks[tx + 16*j][d];
                s[0][j] += a0.x*b.x + a0.y*b.y + a0.z*b.z + a0.w*b.w;
                s[1][j] += a1.x*b.x + a1.y*b.y + a1.z*b.z + a1.w*b.w;
            }
        }
        #pragma unroll
        for (int j = 0; j < 4; j++) {
            float p0 = expf(s[0][j] * 0.125f);
            float p1 = expf(s[1][j] * 0.125f);
            Ps[ty][tx + 16*j]      = p0;
            Ps[ty + 16][tx + 16*j] = p1;
        }
        __syncthreads();

        // O += P @ V   (V tile == K tile).  o columns: d = tx*4 + j
        #pragma unroll
        for (int c = 0; c < 64; c++) {
            float p0 = Ps[ty][c];
            float p1 = Ps[ty + 16][c];
            float4 b = *(const float4*)&Ks[c][tx*4];
            o[0][0] += p0*b.x; o[0][1] += p0*b.y; o[0][2] += p0*b.z; o[0][3] += p0*b.w;
            o[1][0] += p1*b.x; o[1][1] += p1*b.y; o[1][2] += p1*b.z; o[1][3] += p1*b.w;
        }
        // deterministic rowsum (one thread per row)
        if (tid < 32) {
            float acc = 0.f;
            #pragma unroll
            for (int c = 0; c < 64; c++) acc += Ps[tid][c];
            rsum += acc;
        }
    }
    if (tid < 32) rs[tid] = rsum;
    __syncthreads();

    #pragma unroll
    for (int i = 0; i < 2; i++) {
        int q = q0 + ty + 16*i;
        float inv = 1.f / rs[ty + 16*i];
        #pragma unroll
        for (int j = 0; j < 4; j++) {
            int d = tx*4 + j;
            size_t gi = (size_t)q*DM + h*HD + d;
            g_res[gi] = x[gi] + o[i][j] * inv;
        }
    }
}

// ---------------- gate: softmax over 8 logits, top-2 ----------------
__global__ void __launch_bounds__(64) gate_kernel(const float* __restrict__ gate_w)
{
    int n = blockIdx.x;
    int tid = threadIdx.x;        // 64
    int e = tid >> 3, lane = tid & 7;
    const float* xr = g_xf + (size_t)n*DM;
    const float* wr = gate_w + (size_t)e*DM;
    float sum = 0.f;
    for (int d = lane; d < DM; d += 8) sum += xr[d] * wr[d];
    __shared__ float part[8][8];
    __shared__ float logits[8];
    part[e][lane] = sum;
    __syncthreads();
    if (lane == 0) {
        float l = 0.f;
        #pragma unroll
        for (int i = 0; i < 8; i++) l += part[e][i];
        logits[e] = l;
    }
    __syncthreads();
    if (tid == 0) {
        float m = -1e30f;
        #pragma unroll
        for (int i = 0; i < NE; i++) m = fmaxf(m, logits[i]);
        float p[NE]; float s = 0.f;
        #pragma unroll
        for (int i = 0; i < NE; i++) { p[i] = expf(logits[i] - m); s += p[i]; }
        float invs = 1.f / s;
        int e0 = -1, e1 = -1; float v0 = -1.f, v1 = -1.f;
        #pragma unroll
        for (int i = 0; i < NE; i++) {
            float v = p[i] * invs;
            if (v > v0) { v1 = v0; e1 = e0; v0 = v; e0 = i; }
            else if (v > v1) { v1 = v; e1 = i; }
        }
        g_idx[2*n]     = e0;
        g_idx[2*n + 1] = e1;
        g_wts[2*n]     = fmaxf(v0, 1e-7f);
        g_wts[2*n + 1] = fmaxf(v1, 1e-7f);
    }
}

// ---------------- count + exclusive scan ----------------
__global__ void scan_kernel()
{
    __shared__ int cnt[NE];
    if (threadIdx.x < NE) { cnt[threadIdx.x] = 0; g_fill[threadIdx.x] = 0; }
    __syncthreads();
    for (int i = threadIdx.x; i < NSLOT; i += 256) atomicAdd(&cnt[g_idx[i]], 1);
    __syncthreads();
    if (threadIdx.x == 0) {
        int off = 0;
        for (int e = 0; e < NE; e++) { g_counts[e] = cnt[e]; g_offsets[e] = off; off += cnt[e]; }
    }
}

__global__ void scatter_kernel()
{
    int i = blockIdx.x * 256 + threadIdx.x;
    if (i >= NSLOT) return;
    int e = g_idx[i];
    int p = atomicAdd(&g_fill[e], 1);
    g_list[g_offsets[e] + p] = i;   // i = token*2 + slot
}

// ---------------- h = silu(a) * g ----------------
__global__ void silu_mul_kernel()
{
    int i = blockIdx.x * 256 + threadIdx.x;
    float a = g_a[i];
    g_h[i] = (a / (1.f + expf(-a))) * g_gv[i];
}

// ---------------- generic SGEMM: C = A * B^T (+epilogue) ----------------
// MODE 0: fc1  : A=g_xf         B=fc1_w  -> g_t     silu(acc+bias)
// MODE 1: fc2  : A=g_t          B=fc2_w  -> out     acc+bias+res+yk0+yk1
// MODE 2: w1   : A=g_xf(gather) B=w1[e]  -> g_a     acc+b1
// MODE 3: w3   : A=g_xf(gather) B=w3[e]  -> g_gv    acc+b3
// MODE 4: w2   : A=g_h(compact) B=w2[e]  -> g_yk    wts*(acc+b2) scatter
template<int MODE>
__global__ void __launch_bounds__(256) sgemm_kernel(const float* __restrict__ B,
                                                    float* __restrict__ C,
                                                    const float* __restrict__ bias)
{
    const int KD  = (MODE==1) ? ISH : (MODE==4 ? NI : DM);
    const int NN  = (MODE==0) ? ISH : ((MODE==2||MODE==3) ? NI : DM);
    const int LDA = (MODE==1) ? ISH : (MODE==4 ? NI : DM);

    int m0 = blockIdx.y * 128;
    int n0 = blockIdx.x * 128;
    int M  = SQ;
    int moff = 0;
    const float* Bb = B;
    const float* biasb = bias;

    if (MODE >= 2) {
        int e = blockIdx.z;
        int cnt = g_counts[e];
        if (m0 >= cnt) return;
        M = cnt;
        moff = g_offsets[e];
        Bb = B + (size_t)e * NN * KD;
        biasb = bias + (size_t)e * NN;
    }

    const float* Abase = (MODE==1) ? g_t : (MODE==4 ? g_h : g_xf);

    __shared__ __align__(16) float Asm[16][132];
    __shared__ __align__(16) float Bsm[16][132];

    int tid = threadIdx.x;
    int tx = tid & 15, ty = tid >> 4;
    int lm = tid >> 2;            // 0..63
    int lk = (tid & 3) << 2;      // 0,4,8,12

    const float* arow[2];
    const float* brow[2];
    #pragma unroll
    for (int p = 0; p < 2; p++) {
        int m  = m0 + p*64 + lm;
        int mc = (m < M) ? m : (M - 1);
        if (MODE == 2 || MODE == 3)
            arow[p] = Abase + (size_t)(g_list[moff + mc] >> 1) * LDA;
        else if (MODE == 4)
            arow[p] = Abase + (size_t)(moff + mc) * LDA;
        else
            arow[p] = Abase + (size_t)mc * LDA;
        brow[p] = Bb + (size_t)(n0 + p*64 + lm) * KD;
    }

    float acc[8][8] = {};

    for (int k0 = 0; k0 < KD; k0 += 16) {
        #pragma unroll
        for (int p = 0; p < 2; p++) {
            float4 v = *(const float4*)(arow[p] + k0 + lk);
            Asm[lk+0][p*64+lm] = v.x; Asm[lk+1][p*64+lm] = v.y;
            Asm[lk+2][p*64+lm] = v.z; Asm[lk+3][p*64+lm] = v.w;
            float4 w = *(const float4*)(brow[p] + k0 + lk);
            Bsm[lk+0][p*64+lm] = w.x; Bsm[lk+1][p*64+lm] = w.y;
            Bsm[lk+2][p*64+lm] = w.z; Bsm[lk+3][p*64+lm] = w.w;
        }
        __syncthreads();
        #pragma unroll
        for (int kk = 0; kk < 16; kk++) {
            float4 a0 = *(const float4*)&Asm[kk][ty*8];
            float4 a1 = *(const float4*)&Asm[kk][ty*8 + 4];
            float4 b0 = *(const float4*)&Bsm[kk][tx*8];
            float4 b1 = *(const float4*)&Bsm[kk][tx*8 + 4];
            float av[8] = {a0.x,a0.y,a0.z,a0.w,a1.x,a1.y,a1.z,a1.w};
            float bv[8] = {b0.x,b0.y,b0.z,b0.w,b1.x,b1.y,b1.z,b1.w};
            #pragma unroll
            for (int i = 0; i < 8; i++)
                #pragma unroll
                for (int j = 0; j < 8; j++)
                    acc[i][j] += av[i] * bv[j];
        }
        __syncthreads();
    }

    #pragma unroll
    for (int i = 0; i < 8; i++) {
        int r = m0 + ty*8 + i;
        if (r >= M) break;
        #pragma unroll
        for (int j = 0; j < 8; j++) {
            int c = n0 + tx*8 + j;
            float v = acc[i][j];
            if (MODE == 0) {
                v += bias[c];
                v = v / (1.f + expf(-v));
                g_t[(size_t)r*ISH + c] = v;
            } else if (MODE == 1) {
                v += bias[c] + g_res[(size_t)r*DM + c]
                   + g_yk[(size_t)(2*r)*DM + c] + g_yk[(size_t)(2*r+1)*DM + c];
                C[(size_t)r*DM + c] = v;
            } else if (MODE == 2) {
                g_a[(size_t)(moff + r)*NI + c] = v + biasb[c];
            } else if (MODE == 3) {
                g_gv[(size_t)(moff + r)*NI + c] = v + biasb[c];
            } else { // MODE == 4
                int code = g_list[moff + r];
                g_yk[(size_t)code*DM + c] = g_wts[code] * (v + biasb[c]);
            }
        }
    }
}

// ---------------- launch ----------------
extern "C" void kernel_launch(void* const* d_in, const int* in_sizes, int n_in,
                              void* d_out, int out_size)
{
    const float* x       = (const float*)d_in[0];
    const float* norm1_w = (const float*)d_in[1];
    const float* norm3_w = (const float*)d_in[2];
    const float* gate_w  = (const float*)d_in[3];
    const float* w1      = (const float*)d_in[4];
    const float* b1      = (const float*)d_in[5];
    const float* w2      = (const float*)d_in[6];
    const float* b2      = (const float*)d_in[7];
    const float* w3      = (const float*)d_in[8];
    const float* b3      = (const float*)d_in[9];
    const float* fc1_w   = (const float*)d_in[10];
    const float* fc1_b   = (const float*)d_in[11];
    const float* fc2_w   = (const float*)d_in[12];
    const float* fc2_b   = (const float*)d_in[13];
    float* out = (float*)d_out;

    // 1. xn = rmsnorm(x)
    rmsnorm_kernel<0><<<SQ, 256>>>(x, norm1_w);
    // 2. res = x + attn(xn)
    attn_kernel<<<dim3(SQ/32, NH), 256>>>(x);
    // 3. xf = rmsnorm(res)
    rmsnorm_kernel<1><<<SQ, 256>>>(nullptr, norm3_w);
    // 4. gate -> idx/wts
    gate_kernel<<<SQ, 64>>>(gate_w);
    // 5. counts + offsets, 6. scatter lists
    scan_kernel<<<1, 256>>>();
    scatter_kernel<<<NSLOT/256, 256>>>();
    // 7. expert up projections (gathered)
    sgemm_kernel<2><<<dim3(NI/128, 32, NE), 256>>>(w1, nullptr, b1);
    sgemm_kernel<3><<<dim3(NI/128, 32, NE), 256>>>(w3, nullptr, b3);
    // 8. h = silu(a)*g
    silu_mul_kernel<<<(NSLOT*NI)/256, 256>>>();
    // 9. expert down projection -> weighted scatter into yk
    sgemm_kernel<4><<<dim3(DM/128, 32, NE), 256>>>(w2, nullptr, b2);
    // 10. shared expert fc1 (silu)
    sgemm_kernel<0><<<dim3(ISH/128, SQ/128), 256>>>(fc1_w, nullptr, fc1_b);
    // 11. fc2 + final combine: out = res + z + yk0 + yk1
    sgemm_kernel<1><<<dim3(DM/128, SQ/128), 256>>>(fc2_w, out, fc2_b);
}

// round 3
// speedup vs baseline: 1.2736x; 1.2736x over previous
#include <cuda_runtime.h>
#include <math.h>
#include <stdint.h>

#define SQ   2048
#define DM   768
#define NH   12
#define HD   64
#define NE   8
#define NI   1024
#define ISH  2048
#define NSLOT (2*SQ)

// ---------------- device scratch ----------------
__device__ __align__(16) float g_xn [SQ*DM];
__device__ __align__(16) float g_res[SQ*DM];
__device__ __align__(16) float g_xf [SQ*DM];
__device__ __align__(16) float g_t  [SQ*ISH];
__device__ __align__(16) float g_a  [NSLOT*NI];
__device__ __align__(16) float g_gv [NSLOT*NI];
__device__ __align__(16) float g_h  [NSLOT*NI];
__device__ __align__(16) float g_yk [NSLOT*DM];
__device__ int   g_idx[NSLOT];
__device__ float g_wts[NSLOT];
__device__ int   g_counts[NE];
__device__ int   g_offsets[NE];
__device__ int   g_fill[NE];
__device__ int   g_list[NSLOT];

__device__ __forceinline__ float silu_f(float a){ return a / (1.f + expf(-a)); }

__device__ __forceinline__ uint32_t tf32c(float f){
    uint32_t u; asm("cvt.rna.tf32.f32 %0, %1;" : "=r"(u) : "f"(f)); return u;
}
__device__ __forceinline__ void mma8(float* d, const uint32_t* a, const uint32_t* b){
    asm volatile("mma.sync.aligned.m16n8k8.row.col.f32.tf32.tf32.f32 "
        "{%0,%1,%2,%3}, {%4,%5,%6,%7}, {%8,%9}, {%0,%1,%2,%3};"
        : "+f"(d[0]), "+f"(d[1]), "+f"(d[2]), "+f"(d[3])
        : "r"(a[0]), "r"(a[1]), "r"(a[2]), "r"(a[3]), "r"(b[0]), "r"(b[1]));
}
// swizzled shared access: element (row, k) of a 128x32 tile
__device__ __forceinline__ uint32_t ldsm(const uint32_t* base, int row, int k){
    return base[row*32 + (k ^ ((row & 7) << 2))];
}

// ---------------- rmsnorm ----------------
template<int WHICH>
__global__ void __launch_bounds__(256) rmsnorm_kernel(const float* __restrict__ x,
                                                      const float* __restrict__ w)
{
    int n = blockIdx.x;
    const float* row = (WHICH == 0) ? (x + (size_t)n*DM) : (g_res + (size_t)n*DM);
    float* out = (WHICH == 0) ? (g_xn + (size_t)n*DM) : (g_xf + (size_t)n*DM);

    float ss = 0.f;
    for (int d = threadIdx.x; d < DM; d += 256) { float v = row[d]; ss += v*v; }

    __shared__ float red[8];
    #pragma unroll
    for (int o = 16; o; o >>= 1) ss += __shfl_down_sync(0xffffffffu, ss, o);
    if ((threadIdx.x & 31) == 0) red[threadIdx.x >> 5] = ss;
    __syncthreads();
    if (threadIdx.x < 8) {
        ss = red[threadIdx.x];
        #pragma unroll
        for (int o = 4; o; o >>= 1) ss += __shfl_down_sync(0xffu, ss, o);
        if (threadIdx.x == 0) red[0] = ss;
    }
    __syncthreads();
    float inv = rsqrtf(red[0] * (1.0f/DM) + 1e-5f);
    for (int d = threadIdx.x; d < DM; d += 256) out[d] = row[d] * inv * w[d];
}

// ---------------- attention (flash-style, no max-subtract) ----------------
__global__ void __launch_bounds__(256) attn_kernel(const float* __restrict__ x)
{
    int q0 = blockIdx.x * 32;
    int h  = blockIdx.y;

    __shared__ __align__(16) float Qs[32][68];
    __shared__ __align__(16) float Ks[64][68];
    __shared__ __align__(16) float Ps[32][68];
    __shared__ float rs[32];

    int tid = threadIdx.x;
    int tx = tid & 15, ty = tid >> 4;

    {
        int r = tid >> 3;
        int c = (tid & 7) * 8;
        const float* src = g_xn + (size_t)(q0 + r)*DM + h*HD + c;
        *(float4*)&Qs[r][c]     = *(const float4*)src;
        *(float4*)&Qs[r][c + 4] = *(const float4*)(src + 4);
    }

    float o[2][4] = {};
    float rsum = 0.f;

    for (int kt = 0; kt < SQ/64; kt++) {
        int k0 = kt * 64;
        __syncthreads();
        {
            int r = tid >> 2;
            int c = (tid & 3) * 16;
            const float* src = g_xn + (size_t)(k0 + r)*DM + h*HD + c;
            #pragma unroll
            for (int v = 0; v < 4; v++)
                *(float4*)&Ks[r][c + v*4] = *(const float4*)(src + v*4);
        }
        __syncthreads();

        float s[2][4] = {};
        #pragma unroll
        for (int d = 0; d < HD; d += 4) {
            float4 a0 = *(const float4*)&Qs[ty][d];
            float4 a1 = *(const float4*)&Qs[ty + 16][d];
            #pragma unroll
            for (int j = 0; j < 4; j++) {
                float4 b = *(const float4*)&Ks[tx + 16*j][d];
                s[0][j] += a0.x*b.x + a0.y*b.y + a0.z*b.z + a0.w*b.w;
                s[1][j] += a1.x*b.x + a1.y*b.y + a1.z*b.z + a1.w*b.w;
            }
        }
        #pragma unroll
        for (int j = 0; j < 4; j++) {
            Ps[ty][tx + 16*j]      = expf(s[0][j] * 0.125f);
            Ps[ty + 16][tx + 16*j] = expf(s[1][j] * 0.125f);
        }
        __syncthreads();

        #pragma unroll
        for (int c = 0; c < 64; c++) {
            float p0 = Ps[ty][c];
            float p1 = Ps[ty + 16][c];
            float4 b = *(const float4*)&Ks[c][tx*4];
            o[0][0] += p0*b.x; o[0][1] += p0*b.y; o[0][2] += p0*b.z; o[0][3] += p0*b.w;
            o[1][0] += p1*b.x; o[1][1] += p1*b.y; o[1][2] += p1*b.z; o[1][3] += p1*b.w;
        }
        if (tid < 32) {
            float acc = 0.f;
            #pragma unroll
            for (int c = 0; c < 64; c++) acc += Ps[tid][c];
            rsum += acc;
        }
    }
    if (tid < 32) rs[tid] = rsum;
    __syncthreads();

    #pragma unroll
    for (int i = 0; i < 2; i++) {
        int q = q0 + ty + 16*i;
        float inv = 1.f / rs[ty + 16*i];
        #pragma unroll
        for (int j = 0; j < 4; j++) {
            int d = tx*4 + j;
            size_t gi = (size_t)q*DM + h*HD + d;
            g_res[gi] = x[gi] + o[i][j] * inv;
        }
    }
}

// ---------------- gate ----------------
__global__ void __launch_bounds__(64) gate_kernel(const float* __restrict__ gate_w)
{
    int n = blockIdx.x;
    int tid = threadIdx.x;
    int e = tid >> 3, lane = tid & 7;
    const float* xr = g_xf + (size_t)n*DM;
    const float* wr = gate_w + (size_t)e*DM;
    float sum = 0.f;
    for (int d = lane; d < DM; d += 8) sum += xr[d] * wr[d];
    __shared__ float part[8][8];
    __shared__ float logits[8];
    part[e][lane] = sum;
    __syncthreads();
    if (lane == 0) {
        float l = 0.f;
        #pragma unroll
        for (int i = 0; i < 8; i++) l += part[e][i];
        logits[e] = l;
    }
    __syncthreads();
    if (tid == 0) {
        float m = -1e30f;
        #pragma unroll
        for (int i = 0; i < NE; i++) m = fmaxf(m, logits[i]);
        float p[NE]; float s = 0.f;
        #pragma unroll
        for (int i = 0; i < NE; i++) { p[i] = expf(logits[i] - m); s += p[i]; }
        float invs = 1.f / s;
        int e0 = -1, e1 = -1; float v0 = -1.f, v1 = -1.f;
        #pragma unroll
        for (int i = 0; i < NE; i++) {
            float v = p[i] * invs;
            if (v > v0) { v1 = v0; e1 = e0; v0 = v; e0 = i; }
            else if (v > v1) { v1 = v; e1 = i; }
        }
        g_idx[2*n]     = e0;
        g_idx[2*n + 1] = e1;
        g_wts[2*n]     = fmaxf(v0, 1e-7f);
        g_wts[2*n + 1] = fmaxf(v1, 1e-7f);
    }
}

// ---------------- count + scan + scatter ----------------
__global__ void scan_kernel()
{
    __shared__ int cnt[NE];
    if (threadIdx.x < NE) { cnt[threadIdx.x] = 0; g_fill[threadIdx.x] = 0; }
    __syncthreads();
    for (int i = threadIdx.x; i < NSLOT; i += 256) atomicAdd(&cnt[g_idx[i]], 1);
    __syncthreads();
    if (threadIdx.x == 0) {
        int off = 0;
        for (int e = 0; e < NE; e++) { g_counts[e] = cnt[e]; g_offsets[e] = off; off += cnt[e]; }
    }
}

__global__ void scatter_kernel()
{
    int i = blockIdx.x * 256 + threadIdx.x;
    if (i >= NSLOT) return;
    int e = g_idx[i];
    int p = atomicAdd(&g_fill[e], 1);
    g_list[g_offsets[e] + p] = i;
}

// ---------------- h = silu(a) * g ----------------
__global__ void silu_mul_kernel()
{
    int i = blockIdx.x * 256 + threadIdx.x;
    float a = g_a[i];
    g_h[i] = silu_f(a) * g_gv[i];
}

// ---------------- tf32 mma.sync GEMM: C = A * B^T (+ fused epilogues) ----------------
// MODE 0: fc1 : A=g_xf          B=fc1_w -> g_t            silu(acc+bias)
// MODE 1: fc2 : A=g_t           B=fc2_w -> out            acc+bias+res+yk0+yk1
// MODE 2: up  : A=g_xf (gather) B=w[e]  -> g_a/g_gv (TGT) acc+bias
// MODE 3: dn  : A=g_h (compact) B=w2[e] -> g_yk           wts*(acc+bias) scatter
template<int MODE, int TGT>
__global__ void __launch_bounds__(256) mma_gemm(const float* __restrict__ Bw,
                                                float* __restrict__ Cout,
                                                const float* __restrict__ bias)
{
    constexpr int KD = (MODE==1) ? ISH : (MODE==3 ? NI : DM);
    constexpr int NC = KD / 32;
    constexpr int NN = (MODE==0) ? ISH : (MODE==2 ? NI : DM);

    int m0 = blockIdx.y * 128;
    int n0 = blockIdx.x * 128;
    int M = SQ, moff = 0;
    const float* Bb = Bw;
    const float* bb = bias;

    if (MODE >= 2) {
        int e = blockIdx.z;
        int cnt = g_counts[e];
        if (m0 >= cnt) return;
        M = cnt; moff = g_offsets[e];
        Bb = Bw + (size_t)e * NN * KD;
        bb = bias + (size_t)e * NN;
    }

    extern __shared__ __align__(16) uint32_t smu[];
    uint32_t* sA[2] = { smu,        smu + 4096 };
    uint32_t* sB[2] = { smu + 8192, smu + 12288 };

    int tid = threadIdx.x, lane = tid & 31, wid = tid >> 5;
    int wm = wid & 3, wn = wid >> 2;
    int gid = lane >> 2, qid = lane & 3;

    // ---- loader: 2 threads per row, 16 floats each ----
    int r  = tid >> 1;
    int hf = tid & 1;
    int mrow = m0 + r; if (mrow > M - 1) mrow = M - 1;
    const float* arow;
    if      (MODE == 2) arow = g_xf + (size_t)(g_list[moff + mrow] >> 1) * DM;
    else if (MODE == 3) arow = g_h  + (size_t)(moff + mrow) * NI;
    else if (MODE == 1) arow = g_t  + (size_t)mrow * ISH;
    else                arow = g_xf + (size_t)mrow * DM;
    arow += hf * 16;
    const float* brow = Bb + (size_t)(n0 + r) * KD + hf * 16;

    uint32_t so[4];
    #pragma unroll
    for (int i = 0; i < 4; i++) {
        int k0 = hf*16 + i*4;
        so[i] = (uint32_t)(r*32 + (k0 ^ ((r & 7) << 2)));
    }

    float4 pa[4], pb[4];
    #pragma unroll
    for (int i = 0; i < 4; i++) {
        pa[i] = *(const float4*)(arow + i*4);
        pb[i] = *(const float4*)(brow + i*4);
    }

    float acc[2][8][4] = {};

    for (int kc = 0; kc < NC; kc++) {
        int s = kc & 1;
        #pragma unroll
        for (int i = 0; i < 4; i++) {
            uint4 ua = make_uint4(tf32c(pa[i].x), tf32c(pa[i].y), tf32c(pa[i].z), tf32c(pa[i].w));
            uint4 ub = make_uint4(tf32c(pb[i].x), tf32c(pb[i].y), tf32c(pb[i].z), tf32c(pb[i].w));
            *(uint4*)&sA[s][so[i]] = ua;
            *(uint4*)&sB[s][so[i]] = ub;
        }
        if (kc + 1 < NC) {
            int k0 = (kc + 1) * 32;
            #pragma unroll
            for (int i = 0; i < 4; i++) {
                pa[i] = *(const float4*)(arow + k0 + i*4);
                pb[i] = *(const float4*)(brow + k0 + i*4);
            }
        }
        __syncthreads();

        const uint32_t* cA = sA[s];
        const uint32_t* cB = sB[s];
        #pragma unroll
        for (int kk = 0; kk < 4; kk++) {
            int kb = kk * 8;
            uint32_t af[2][4], bf[8][2];
            #pragma unroll
            for (int mi = 0; mi < 2; mi++) {
                int r0 = 32*wm + 16*mi + gid;
                af[mi][0] = ldsm(cA, r0,     kb + qid);
                af[mi][1] = ldsm(cA, r0 + 8, kb + qid);
                af[mi][2] = ldsm(cA, r0,     kb + qid + 4);
                af[mi][3] = ldsm(cA, r0 + 8, kb + qid + 4);
            }
            #pragma unroll
            for (int ni = 0; ni < 8; ni++) {
                int n = 64*wn + 8*ni + gid;
                bf[ni][0] = ldsm(cB, n, kb + qid);
                bf[ni][1] = ldsm(cB, n, kb + qid + 4);
            }
            #pragma unroll
            for (int mi = 0; mi < 2; mi++)
                #pragma unroll
                for (int ni = 0; ni < 8; ni++)
                    mma8(acc[mi][ni], af[mi], bf[ni]);
        }
        __syncthreads();
    }

    // ---- epilogue ----
    #pragma unroll
    for (int mi = 0; mi < 2; mi++) {
        #pragma unroll
        for (int half = 0; half < 2; half++) {
            int row = m0 + 32*wm + 16*mi + gid + 8*half;
            if (MODE >= 2 && row >= M) continue;
            #pragma unroll
            for (int ni = 0; ni < 8; ni++) {
                float v0 = acc[mi][ni][2*half + 0];
                float v1 = acc[mi][ni][2*half + 1];
                int col = n0 + 64*wn + 8*ni + 2*qid;
                float b0 = bb[col], b1 = bb[col + 1];
                if (MODE == 0) {
                    float2 o = make_float2(silu_f(v0 + b0), silu_f(v1 + b1));
                    *(float2*)&g_t[(size_t)row*ISH + col] = o;
                } else if (MODE == 1) {
                    float2 rr = *(const float2*)&g_res[(size_t)row*DM + col];
                    float2 a0 = *(const float2*)&g_yk[(size_t)(2*row)*DM + col];
                    float2 a1 = *(const float2*)&g_yk[(size_t)(2*row + 1)*DM + col];
                    float2 o  = make_float2(v0 + b0 + rr.x + a0.x + a1.x,
                                            v1 + b1 + rr.y + a0.y + a1.y);
                    *(float2*)&Cout[(size_t)row*DM + col] = o;
                } else if (MODE == 2) {
                    float* dst = (TGT ? g_gv : g_a) + (size_t)(moff + row)*NI + col;
                    *(float2*)dst = make_float2(v0 + b0, v1 + b1);
                } else { // MODE 3
                    int code = g_list[moff + row];
                    float w = g_wts[code];
                    float2 o = make_float2(w*(v0 + b0), w*(v1 + b1));
                    *(float2*)&g_yk[(size_t)code*DM + col] = o;
                }
            }
        }
    }
}

// ---------------- launch ----------------
extern "C" void kernel_launch(void* const* d_in, const int* in_sizes, int n_in,
                              void* d_out, int out_size)
{
    const float* x       = (const float*)d_in[0];
    const float* norm1_w = (const float*)d_in[1];
    const float* norm3_w = (const float*)d_in[2];
    const float* gate_w  = (const float*)d_in[3];
    const float* w1      = (const float*)d_in[4];
    const float* b1      = (const float*)d_in[5];
    const float* w2      = (const float*)d_in[6];
    const float* b2      = (const float*)d_in[7];
    const float* w3      = (const float*)d_in[8];
    const float* b3      = (const float*)d_in[9];
    const float* fc1_w   = (const float*)d_in[10];
    const float* fc1_b   = (const float*)d_in[11];
    const float* fc2_w   = (const float*)d_in[12];
    const float* fc2_b   = (const float*)d_in[13];
    float* out = (float*)d_out;

    const int SMB = 4 * 4096 * 4;   // 65536 bytes
    static bool attr_done = false;
    if (!attr_done) {
        cudaFuncSetAttribute(mma_gemm<0,0>, cudaFuncAttributeMaxDynamicSharedMemorySize, SMB);
        cudaFuncSetAttribute(mma_gemm<1,0>, cudaFuncAttributeMaxDynamicSharedMemorySize, SMB);
        cudaFuncSetAttribute(mma_gemm<2,0>, cudaFuncAttributeMaxDynamicSharedMemorySize, SMB);
        cudaFuncSetAttribute(mma_gemm<2,1>, cudaFuncAttributeMaxDynamicSharedMemorySize, SMB);
        cudaFuncSetAttribute(mma_gemm<3,0>, cudaFuncAttributeMaxDynamicSharedMemorySize, SMB);
        attr_done = true;
    }

    rmsnorm_kernel<0><<<SQ, 256>>>(x, norm1_w);
    attn_kernel<<<dim3(SQ/32, NH), 256>>>(x);
    rmsnorm_kernel<1><<<SQ, 256>>>(nullptr, norm3_w);
    gate_kernel<<<SQ, 64>>>(gate_w);
    scan_kernel<<<1, 256>>>();
    scatter_kernel<<<NSLOT/256, 256>>>();

    // experts up: w1 -> g_a, w3 -> g_gv
    mma_gemm<2,0><<<dim3(NI/128, 32, NE), 256, SMB>>>(w1, nullptr, b1);
    mma_gemm<2,1><<<dim3(NI/128, 32, NE), 256, SMB>>>(w3, nullptr, b3);
    silu_mul_kernel<<<(NSLOT*NI)/256, 256>>>();
    // experts down -> g_yk (route-weighted scatter)
    mma_gemm<3,0><<<dim3(DM/128, 32, NE), 256, SMB>>>(w2, nullptr, b2);
    // shared fc1 (silu) -> g_t
    mma_gemm<0,0><<<dim3(ISH/128, SQ/128), 256, SMB>>>(fc1_w, nullptr, fc1_b);
    // fc2 + final combine -> out
    mma_gemm<1,0><<<dim3(DM/128, SQ/128), 256, SMB>>>(fc2_w, out, fc2_b);
}

// round 4
// speedup vs baseline: 1.8181x; 1.4275x over previous
#include <cuda_runtime.h>
#include <math.h>
#include <stdint.h>

#define SQ   2048
#define DM   768
#define NH   12
#define HD   64
#define NE   8
#define NI   1024
#define ISH  2048
#define NSLOT (2*SQ)

// ---------------- device scratch ----------------
__device__ __align__(16) float g_xn [SQ*DM];
__device__ __align__(16) float g_res[SQ*DM];
__device__ __align__(16) float g_xf [SQ*DM];
__device__ __align__(16) float g_t  [SQ*ISH];
__device__ __align__(16) float g_a  [NSLOT*NI];
__device__ __align__(16) float g_gv [NSLOT*NI];
__device__ __align__(16) float g_h  [NSLOT*NI];
__device__ __align__(16) float g_yk [NSLOT*DM];
__device__ int   g_idx[NSLOT];
__device__ float g_wts[NSLOT];
__device__ int   g_counts[NE];
__device__ int   g_offsets[NE];
__device__ int   g_fill[NE];
__device__ int   g_list[NSLOT];

__device__ __forceinline__ float silu_f(float a){ return a / (1.f + expf(-a)); }

__device__ __forceinline__ uint32_t tf32c(float f){
    uint32_t u; asm("cvt.rna.tf32.f32 %0, %1;" : "=r"(u) : "f"(f)); return u;
}
__device__ __forceinline__ void mma8(float* d, const uint32_t* a, const uint32_t* b){
    asm volatile("mma.sync.aligned.m16n8k8.row.col.f32.tf32.tf32.f32 "
        "{%0,%1,%2,%3}, {%4,%5,%6,%7}, {%8,%9}, {%0,%1,%2,%3};"
        : "+f"(d[0]), "+f"(d[1]), "+f"(d[2]), "+f"(d[3])
        : "r"(a[0]), "r"(a[1]), "r"(a[2]), "r"(a[3]), "r"(b[0]), "r"(b[1]));
}
// swizzled shared access for 32-wide GEMM tiles
__device__ __forceinline__ uint32_t ldsm(const uint32_t* base, int row, int k){
    return base[row*32 + (k ^ ((row & 7) << 2))];
}
// swizzled shared access for 64-wide attention tiles
__device__ __forceinline__ uint32_t lds64(const uint32_t* base, int r, int c){
    return base[r*64 + (c ^ ((r & 7) << 2))];
}

// fast exp(s*0.125): 2^(s*0.125*log2e) via poly + exponent insert.
// deterministic, FMA/ALU-pipe-only (no MUFU). rel err ~2.4e-6.
__device__ __forceinline__ float fexps(float s){
    float y = s * 0.18033688011112042f;      // 0.125 * log2(e)
    y = fminf(fmaxf(y, -126.f), 126.f);
    float r = y + 12582912.f;                // round to nearest int (magic)
    float f = y - (r - 12582912.f);          // f in [-0.5, 0.5]
    float p = 1.3333558146e-3f;
    p = fmaf(p, f, 9.6181291776e-3f);
    p = fmaf(p, f, 5.5504108664e-2f);
    p = fmaf(p, f, 2.4022650696e-1f);
    p = fmaf(p, f, 6.9314718056e-1f);
    p = fmaf(p, f, 1.0f);
    return __int_as_float(__float_as_int(p) + (__float_as_int(r) << 23));
}

// ---------------- rmsnorm ----------------
template<int WHICH>
__global__ void __launch_bounds__(256) rmsnorm_kernel(const float* __restrict__ x,
                                                      const float* __restrict__ w)
{
    int n = blockIdx.x;
    const float* row = (WHICH == 0) ? (x + (size_t)n*DM) : (g_res + (size_t)n*DM);
    float* out = (WHICH == 0) ? (g_xn + (size_t)n*DM) : (g_xf + (size_t)n*DM);

    float ss = 0.f;
    for (int d = threadIdx.x; d < DM; d += 256) { float v = row[d]; ss += v*v; }

    __shared__ float red[8];
    #pragma unroll
    for (int o = 16; o; o >>= 1) ss += __shfl_down_sync(0xffffffffu, ss, o);
    if ((threadIdx.x & 31) == 0) red[threadIdx.x >> 5] = ss;
    __syncthreads();
    if (threadIdx.x < 8) {
        ss = red[threadIdx.x];
        #pragma unroll
        for (int o = 4; o; o >>= 1) ss += __shfl_down_sync(0xffu, ss, o);
        if (threadIdx.x == 0) red[0] = ss;
    }
    __syncthreads();
    float inv = rsqrtf(red[0] * (1.0f/DM) + 1e-5f);
    for (int d = threadIdx.x; d < DM; d += 256) out[d] = row[d] * inv * w[d];
}

// ---------------- attention: tf32 mma + fast exp ----------------
// block: 64 q-rows x 1 head. 8 warps in 4x2 grid (wm: 16 rows, wn: 32 cols).
__global__ void __launch_bounds__(256) attn_mma_kernel(const float* __restrict__ x)
{
    int q0 = blockIdx.x * 64;
    int h  = blockIdx.y;

    extern __shared__ __align__(16) uint32_t sm[];
    uint32_t* Qs = sm;           // 64x64 tf32
    uint32_t* Ks = sm + 4096;
    uint32_t* Vt = sm + 8192;    // transposed K tile [d][c]
    uint32_t* Ps = sm + 12288;
    float* rssm  = (float*)(sm + 16384);   // [2][64]

    int tid = threadIdx.x, lane = tid & 31, wid = tid >> 5;
    int wm = wid & 3, wn = wid >> 2, gid = lane >> 2, qid = lane & 3;

    // load Q tile (64x64) -> tf32 swizzled
    {
        int r = tid >> 2, c4 = (tid & 3) * 16;
        const float* src = g_xn + (size_t)(q0 + r)*DM + h*HD + c4;
        #pragma unroll
        for (int j = 0; j < 4; j++) {
            float4 v = *(const float4*)(src + 4*j);
            uint32_t c = (uint32_t)((c4 + 4*j) ^ ((r & 7) << 2));
            uint4 u = make_uint4(tf32c(v.x), tf32c(v.y), tf32c(v.z), tf32c(v.w));
            *(uint4*)&Qs[r*64 + c] = u;
        }
    }

    float acc_o[4][4] = {};
    float rs0 = 0.f, rs1 = 0.f;
    int r0 = wm*16 + gid;

    for (int kt = 0; kt < SQ/64; kt++) {
        __syncthreads();   // prior PV done reading Ks/Vt; Qs ready on iter 0
        // load K tile -> Ks (row-major) and Vt (transposed), tf32 swizzled
        {
            int r = tid >> 2, c4 = (tid & 3) * 16;
            const float* src = g_xn + (size_t)(kt*64 + r)*DM + h*HD + c4;
            #pragma unroll
            for (int j = 0; j < 4; j++) {
                float4 v = *(const float4*)(src + 4*j);
                int d0 = c4 + 4*j;
                uint4 u = make_uint4(tf32c(v.x), tf32c(v.y), tf32c(v.z), tf32c(v.w));
                *(uint4*)&Ks[r*64 + (d0 ^ ((r & 7) << 2))] = u;
                Vt[(d0+0)*64 + (r ^ (((d0+0) & 7) << 2))] = u.x;
                Vt[(d0+1)*64 + (r ^ (((d0+1) & 7) << 2))] = u.y;
                Vt[(d0+2)*64 + (r ^ (((d0+2) & 7) << 2))] = u.z;
                Vt[(d0+3)*64 + (r ^ (((d0+3) & 7) << 2))] = u.w;
            }
        }
        __syncthreads();

        // S = Q K^T (warp tile 16x32)
        float acc_s[4][4] = {};
        #pragma unroll
        for (int kk = 0; kk < 8; kk++) {
            int kb = kk * 8;
            uint32_t af[4];
            af[0] = lds64(Qs, r0,     kb + qid);
            af[1] = lds64(Qs, r0 + 8, kb + qid);
            af[2] = lds64(Qs, r0,     kb + qid + 4);
            af[3] = lds64(Qs, r0 + 8, kb + qid + 4);
            #pragma unroll
            for (int ni = 0; ni < 4; ni++) {
                uint32_t bf[2];
                int n = wn*32 + 8*ni + gid;
                bf[0] = lds64(Ks, n, kb + qid);
                bf[1] = lds64(Ks, n, kb + qid + 4);
                mma8(acc_s[ni], af, bf);
            }
        }

        // P = exp(S/8), partial row sums, store P (tf32) to smem
        float p0 = 0.f, p1 = 0.f;
        #pragma unroll
        for (int ni = 0; ni < 4; ni++) {
            float e0 = fexps(acc_s[ni][0]);
            float e1 = fexps(acc_s[ni][1]);
            float e2 = fexps(acc_s[ni][2]);
            float e3 = fexps(acc_s[ni][3]);
            p0 += e0 + e1;
            p1 += e2 + e3;
            int col = wn*32 + 8*ni + 2*qid;
            uint2 u0 = make_uint2(tf32c(e0), tf32c(e1));
            uint2 u1 = make_uint2(tf32c(e2), tf32c(e3));
            *(uint2*)&Ps[r0*64 + (col ^ ((r0 & 7) << 2))] = u0;
            int r1 = r0 + 8;
            *(uint2*)&Ps[r1*64 + (col ^ ((r1 & 7) << 2))] = u1;
        }
        p0 += __shfl_xor_sync(0xffffffffu, p0, 1);
        p0 += __shfl_xor_sync(0xffffffffu, p0, 2);
        p1 += __shfl_xor_sync(0xffffffffu, p1, 1);
        p1 += __shfl_xor_sync(0xffffffffu, p1, 2);
        rs0 += p0; rs1 += p1;
        __syncthreads();   // P visible to all warps

        // O += P @ V  (B = Vt)
        #pragma unroll
        for (int kk = 0; kk < 8; kk++) {
            int kb = kk * 8;
            uint32_t af[4];
            af[0] = lds64(Ps, r0,     kb + qid);
            af[1] = lds64(Ps, r0 + 8, kb + qid);
            af[2] = lds64(Ps, r0,     kb + qid + 4);
            af[3] = lds64(Ps, r0 + 8, kb + qid + 4);
            #pragma unroll
            for (int ni = 0; ni < 4; ni++) {
                uint32_t bf[2];
                int n = wn*32 + 8*ni + gid;
                bf[0] = lds64(Vt, n, kb + qid);
                bf[1] = lds64(Vt, n, kb + qid + 4);
                mma8(acc_o[ni], af, bf);
            }
        }
    }

    // combine row sums across the two wn halves
    if (qid == 0) {
        rssm[wn*64 + r0]     = rs0;
        rssm[wn*64 + r0 + 8] = rs1;
    }
    __syncthreads();
    float inv0 = 1.f / (rssm[r0]     + rssm[64 + r0]);
    float inv1 = 1.f / (rssm[r0 + 8] + rssm[64 + r0 + 8]);

    #pragma unroll
    for (int ni = 0; ni < 4; ni++) {
        int col = h*HD + wn*32 + 8*ni + 2*qid;
        size_t gi0 = (size_t)(q0 + r0)*DM + col;
        size_t gi1 = (size_t)(q0 + r0 + 8)*DM + col;
        float2 x0 = *(const float2*)&x[gi0];
        float2 x1 = *(const float2*)&x[gi1];
        float2 o0 = make_float2(x0.x + acc_o[ni][0]*inv0, x0.y + acc_o[ni][1]*inv0);
        float2 o1 = make_float2(x1.x + acc_o[ni][2]*inv1, x1.y + acc_o[ni][3]*inv1);
        *(float2*)&g_res[gi0] = o0;
        *(float2*)&g_res[gi1] = o1;
    }
}

// ---------------- gate ----------------
__global__ void __launch_bounds__(64) gate_kernel(const float* __restrict__ gate_w)
{
    int n = blockIdx.x;
    int tid = threadIdx.x;
    int e = tid >> 3, lane = tid & 7;
    const float* xr = g_xf + (size_t)n*DM;
    const float* wr = gate_w + (size_t)e*DM;
    float sum = 0.f;
    for (int d = lane; d < DM; d += 8) sum += xr[d] * wr[d];
    __shared__ float part[8][8];
    __shared__ float logits[8];
    part[e][lane] = sum;
    __syncthreads();
    if (lane == 0) {
        float l = 0.f;
        #pragma unroll
        for (int i = 0; i < 8; i++) l += part[e][i];
        logits[e] = l;
    }
    __syncthreads();
    if (tid == 0) {
        float m = -1e30f;
        #pragma unroll
        for (int i = 0; i < NE; i++) m = fmaxf(m, logits[i]);
        float p[NE]; float s = 0.f;
        #pragma unroll
        for (int i = 0; i < NE; i++) { p[i] = expf(logits[i] - m); s += p[i]; }
        float invs = 1.f / s;
        int e0 = -1, e1 = -1; float v0 = -1.f, v1 = -1.f;
        #pragma unroll
        for (int i = 0; i < NE; i++) {
            float v = p[i] * invs;
            if (v > v0) { v1 = v0; e1 = e0; v0 = v; e0 = i; }
            else if (v > v1) { v1 = v; e1 = i; }
        }
        g_idx[2*n]     = e0;
        g_idx[2*n + 1] = e1;
        g_wts[2*n]     = fmaxf(v0, 1e-7f);
        g_wts[2*n + 1] = fmaxf(v1, 1e-7f);
    }
}

// ---------------- count + scan + scatter ----------------
__global__ void scan_kernel()
{
    __shared__ int cnt[NE];
    if (threadIdx.x < NE) { cnt[threadIdx.x] = 0; g_fill[threadIdx.x] = 0; }
    __syncthreads();
    for (int i = threadIdx.x; i < NSLOT; i += 256) atomicAdd(&cnt[g_idx[i]], 1);
    __syncthreads();
    if (threadIdx.x == 0) {
        int off = 0;
        for (int e = 0; e < NE; e++) { g_counts[e] = cnt[e]; g_offsets[e] = off; off += cnt[e]; }
    }
}

__global__ void scatter_kernel()
{
    int i = blockIdx.x * 256 + threadIdx.x;
    if (i >= NSLOT) return;
    int e = g_idx[i];
    int p = atomicAdd(&g_fill[e], 1);
    g_list[g_offsets[e] + p] = i;
}

// ---------------- h = silu(a) * g ----------------
__global__ void silu_mul_kernel()
{
    int i = blockIdx.x * 256 + threadIdx.x;
    float a = g_a[i];
    g_h[i] = silu_f(a) * g_gv[i];
}

// ---------------- tf32 mma.sync GEMM: C = A * B^T (+ fused epilogues) ----------------
template<int MODE, int TGT>
__global__ void __launch_bounds__(256) mma_gemm(const float* __restrict__ Bw,
                                                float* __restrict__ Cout,
                                                const float* __restrict__ bias)
{
    constexpr int KD = (MODE==1) ? ISH : (MODE==3 ? NI : DM);
    constexpr int NC = KD / 32;
    constexpr int NN = (MODE==0) ? ISH : (MODE==2 ? NI : DM);

    int m0 = blockIdx.y * 128;
    int n0 = blockIdx.x * 128;
    int M = SQ, moff = 0;
    const float* Bb = Bw;
    const float* bb = bias;

    if (MODE >= 2) {
        int e = blockIdx.z;
        int cnt = g_counts[e];
        if (m0 >= cnt) return;
        M = cnt; moff = g_offsets[e];
        Bb = Bw + (size_t)e * NN * KD;
        bb = bias + (size_t)e * NN;
    }

    extern __shared__ __align__(16) uint32_t smu[];
    uint32_t* sA[2] = { smu,        smu + 4096 };
    uint32_t* sB[2] = { smu + 8192, smu + 12288 };

    int tid = threadIdx.x, lane = tid & 31, wid = tid >> 5;
    int wm = wid & 3, wn = wid >> 2;
    int gid = lane >> 2, qid = lane & 3;

    int r  = tid >> 1;
    int hf = tid & 1;
    int mrow = m0 + r; if (mrow > M - 1) mrow = M - 1;
    const float* arow;
    if      (MODE == 2) arow = g_xf + (size_t)(g_list[moff + mrow] >> 1) * DM;
    else if (MODE == 3) arow = g_h  + (size_t)(moff + mrow) * NI;
    else if (MODE == 1) arow = g_t  + (size_t)mrow * ISH;
    else                arow = g_xf + (size_t)mrow * DM;
    arow += hf * 16;
    const float* brow = Bb + (size_t)(n0 + r) * KD + hf * 16;

    uint32_t so[4];
    #pragma unroll
    for (int i = 0; i < 4; i++) {
        int k0 = hf*16 + i*4;
        so[i] = (uint32_t)(r*32 + (k0 ^ ((r & 7) << 2)));
    }

    float4 pa[4], pb[4];
    #pragma unroll
    for (int i = 0; i < 4; i++) {
        pa[i] = *(const float4*)(arow + i*4);
        pb[i] = *(const float4*)(brow + i*4);
    }

    float acc[2][8][4] = {};

    for (int kc = 0; kc < NC; kc++) {
        int s = kc & 1;
        #pragma unroll
        for (int i = 0; i < 4; i++) {
            uint4 ua = make_uint4(tf32c(pa[i].x), tf32c(pa[i].y), tf32c(pa[i].z), tf32c(pa[i].w));
            uint4 ub = make_uint4(tf32c(pb[i].x), tf32c(pb[i].y), tf32c(pb[i].z), tf32c(pb[i].w));
            *(uint4*)&sA[s][so[i]] = ua;
            *(uint4*)&sB[s][so[i]] = ub;
        }
        if (kc + 1 < NC) {
            int k0 = (kc + 1) * 32;
            #pragma unroll
            for (int i = 0; i < 4; i++) {
                pa[i] = *(const float4*)(arow + k0 + i*4);
                pb[i] = *(const float4*)(brow + k0 + i*4);
            }
        }
        __syncthreads();

        const uint32_t* cA = sA[s];
        const uint32_t* cB = sB[s];
        #pragma unroll
        for (int kk = 0; kk < 4; kk++) {
            int kb = kk * 8;
            uint32_t af[2][4], bf[8][2];
            #pragma unroll
            for (int mi = 0; mi < 2; mi++) {
                int rr = 32*wm + 16*mi + gid;
                af[mi][0] = ldsm(cA, rr,     kb + qid);
                af[mi][1] = ldsm(cA, rr + 8, kb + qid);
                af[mi][2] = ldsm(cA, rr,     kb + qid + 4);
                af[mi][3] = ldsm(cA, rr + 8, kb + qid + 4);
            }
            #pragma unroll
            for (int ni = 0; ni < 8; ni++) {
                int n = 64*wn + 8*ni + gid;
                bf[ni][0] = ldsm(cB, n, kb + qid);
                bf[ni][1] = ldsm(cB, n, kb + qid + 4);
            }
            #pragma unroll
            for (int mi = 0; mi < 2; mi++)
                #pragma unroll
                for (int ni = 0; ni < 8; ni++)
                    mma8(acc[mi][ni], af[mi], bf[ni]);
        }
        __syncthreads();
    }

    #pragma unroll
    for (int mi = 0; mi < 2; mi++) {
        #pragma unroll
        for (int half = 0; half < 2; half++) {
            int row = m0 + 32*wm + 16*mi + gid + 8*half;
            if (MODE >= 2 && row >= M) continue;
            #pragma unroll
            for (int ni = 0; ni < 8; ni++) {
                float v0 = acc[mi][ni][2*half + 0];
                float v1 = acc[mi][ni][2*half + 1];
                int col = n0 + 64*wn + 8*ni + 2*qid;
                float b0 = bb[col], b1 = bb[col + 1];
                if (MODE == 0) {
                    float2 o = make_float2(silu_f(v0 + b0), silu_f(v1 + b1));
                    *(float2*)&g_t[(size_t)row*ISH + col] = o;
                } else if (MODE == 1) {
                    float2 rr = *(const float2*)&g_res[(size_t)row*DM + col];
                    float2 a0 = *(const float2*)&g_yk[(size_t)(2*row)*DM + col];
                    float2 a1 = *(const float2*)&g_yk[(size_t)(2*row + 1)*DM + col];
                    float2 o  = make_float2(v0 + b0 + rr.x + a0.x + a1.x,
                                            v1 + b1 + rr.y + a0.y + a1.y);
                    *(float2*)&Cout[(size_t)row*DM + col] = o;
                } else if (MODE == 2) {
                    float* dst = (TGT ? g_gv : g_a) + (size_t)(moff + row)*NI + col;
                    *(float2*)dst = make_float2(v0 + b0, v1 + b1);
                } else {
                    int code = g_list[moff + row];
                    float w = g_wts[code];
                    float2 o = make_float2(w*(v0 + b0), w*(v1 + b1));
                    *(float2*)&g_yk[(size_t)code*DM + col] = o;
                }
            }
        }
    }
}

// ---------------- launch ----------------
extern "C" void kernel_launch(void* const* d_in, const int* in_sizes, int n_in,
                              void* d_out, int out_size)
{
    const float* x       = (const float*)d_in[0];
    const float* norm1_w = (const float*)d_in[1];
    const float* norm3_w = (const float*)d_in[2];
    const float* gate_w  = (const float*)d_in[3];
    const float* w1      = (const float*)d_in[4];
    const float* b1      = (const float*)d_in[5];
    const float* w2      = (const float*)d_in[6];
    const float* b2      = (const float*)d_in[7];
    const float* w3      = (const float*)d_in[8];
    const float* b3      = (const float*)d_in[9];
    const float* fc1_w   = (const float*)d_in[10];
    const float* fc1_b   = (const float*)d_in[11];
    const float* fc2_w   = (const float*)d_in[12];
    const float* fc2_b   = (const float*)d_in[13];
    float* out = (float*)d_out;

    const int SMB  = 4 * 4096 * 4;            // 65536 B (gemm)
    const int SMA  = 16384 * 4 + 512;         // 66048 B (attention)
    static bool attr_done = false;
    if (!attr_done) {
        cudaFuncSetAttribute(mma_gemm<0,0>, cudaFuncAttributeMaxDynamicSharedMemorySize, SMB);
        cudaFuncSetAttribute(mma_gemm<1,0>, cudaFuncAttributeMaxDynamicSharedMemorySize, SMB);
        cudaFuncSetAttribute(mma_gemm<2,0>, cudaFuncAttributeMaxDynamicSharedMemorySize, SMB);
        cudaFuncSetAttribute(mma_gemm<2,1>, cudaFuncAttributeMaxDynamicSharedMemorySize, SMB);
        cudaFuncSetAttribute(mma_gemm<3,0>, cudaFuncAttributeMaxDynamicSharedMemorySize, SMB);
        cudaFuncSetAttribute(attn_mma_kernel, cudaFuncAttributeMaxDynamicSharedMemorySize, SMA);
        attr_done = true;
    }

    rmsnorm_kernel<0><<<SQ, 256>>>(x, norm1_w);
    attn_mma_kernel<<<dim3(SQ/64, NH), 256, SMA>>>(x);
    rmsnorm_kernel<1><<<SQ, 256>>>(nullptr, norm3_w);
    gate_kernel<<<SQ, 64>>>(gate_w);
    scan_kernel<<<1, 256>>>();
    scatter_kernel<<<NSLOT/256, 256>>>();

    mma_gemm<2,0><<<dim3(NI/128, 32, NE), 256, SMB>>>(w1, nullptr, b1);
    mma_gemm<2,1><<<dim3(NI/128, 32, NE), 256, SMB>>>(w3, nullptr, b3);
    silu_mul_kernel<<<(NSLOT*NI)/256, 256>>>();
    mma_gemm<3,0><<<dim3(DM/128, 32, NE), 256, SMB>>>(w2, nullptr, b2);
    mma_gemm<0,0><<<dim3(ISH/128, SQ/128), 256, SMB>>>(fc1_w, nullptr, fc1_b);
    mma_gemm<1,0><<<dim3(DM/128, SQ/128), 256, SMB>>>(fc2_w, out, fc2_b);
}

// round 5
// speedup vs baseline: 2.0012x; 1.1007x over previous
#include <cuda_runtime.h>
#include <math.h>
#include <stdint.h>

#define SQ   2048
#define DM   768
#define NH   12
#define HD   64
#define NE   8
#define NI   1024
#define ISH  2048
#define NSLOT (2*SQ)

// ---------------- device scratch ----------------
__device__ __align__(16) float g_xn [SQ*DM];
__device__ __align__(16) float g_res[SQ*DM];
__device__ __align__(16) float g_xf [SQ*DM];
__device__ __align__(16) float g_t  [SQ*ISH];
__device__ __align__(16) float g_a  [NSLOT*NI];
__device__ __align__(16) float g_gv [NSLOT*NI];
__device__ __align__(16) float g_h  [NSLOT*NI];
__device__ __align__(16) float g_yk [NSLOT*DM];
__device__ float g_logits[SQ*NE];
__device__ int   g_idx[NSLOT];
__device__ float g_wts[NSLOT];
__device__ int   g_counts[NE];
__device__ int   g_offsets[NE];
__device__ int   g_fill[NE];
__device__ int   g_list[NSLOT];

// ---------------- helpers ----------------
__device__ __forceinline__ uint32_t smem_u32(const void* p){
    uint32_t a;
    asm("{ .reg .u64 t; cvta.to.shared.u64 t, %1; cvt.u32.u64 %0, t; }" : "=r"(a) : "l"(p));
    return a;
}
__device__ __forceinline__ uint32_t tf32c(float f){
    uint32_t u; asm("cvt.rna.tf32.f32 %0, %1;" : "=r"(u) : "f"(f)); return u;
}
__device__ __forceinline__ void mma8(float* d, const uint32_t* a, const uint32_t* b){
    asm volatile("mma.sync.aligned.m16n8k8.row.col.f32.tf32.tf32.f32 "
        "{%0,%1,%2,%3}, {%4,%5,%6,%7}, {%8,%9}, {%0,%1,%2,%3};"
        : "+f"(d[0]), "+f"(d[1]), "+f"(d[2]), "+f"(d[3])
        : "r"(a[0]), "r"(a[1]), "r"(a[2]), "r"(a[3]), "r"(b[0]), "r"(b[1]));
}
__device__ __forceinline__ uint32_t ldsm(const uint32_t* base, int row, int k){
    return base[row*32 + (k ^ ((row & 7) << 2))];
}
__device__ __forceinline__ uint32_t lds64(const uint32_t* base, int r, int c){
    return base[r*64 + (c ^ ((r & 7) << 2))];
}
__device__ __forceinline__ void cpasync16(uint32_t dst, const void* src){
    asm volatile("cp.async.cg.shared.global [%0], [%1], 16;" :: "r"(dst), "l"(src) : "memory");
}
#define CP_COMMIT() asm volatile("cp.async.commit_group;" ::: "memory")

// fast 2^y, FMA-pipe only, deterministic, rel err ~2e-6
__device__ __forceinline__ float fexp2n(float y){
    y = fminf(fmaxf(y, -126.f), 126.f);
    float r = y + 12582912.f;
    float f = y - (r - 12582912.f);
    float p = 1.3333558146e-3f;
    p = fmaf(p, f, 9.6181291776e-3f);
    p = fmaf(p, f, 5.5504108664e-2f);
    p = fmaf(p, f, 2.4022650696e-1f);
    p = fmaf(p, f, 6.9314718056e-1f);
    p = fmaf(p, f, 1.0f);
    return __int_as_float(__float_as_int(p) + (__float_as_int(r) << 23));
}
__device__ __forceinline__ float fexps(float s){ return fexp2n(s * 0.18033688011112042f); }
__device__ __forceinline__ float frcp(float x){
    float y = __int_as_float(0x7EF311C3 - __float_as_int(x));
    y = y * (2.f - x*y);
    y = y * (2.f - x*y);
    y = y * (2.f - x*y);
    return y;
}
__device__ __forceinline__ float fsilu(float a){
    float t = fexp2n(-a * 1.4426950408889634f);
    return a * frcp(1.f + t);
}

// ---------------- rmsnorm (WHICH=1 also emits gate logits) ----------------
template<int WHICH>
__global__ void __launch_bounds__(256) rmsnorm_kernel(const float* __restrict__ x,
                                                      const float* __restrict__ w,
                                                      const float* __restrict__ gw)
{
    int n = blockIdx.x;
    int t = threadIdx.x;
    const float* row = (WHICH == 0) ? (x + (size_t)n*DM) : (g_res + (size_t)n*DM);
    float* out = (WHICH == 0) ? (g_xn + (size_t)n*DM) : (g_xf + (size_t)n*DM);

    float v0 = row[t], v1 = row[t+256], v2 = row[t+512];
    float ss = v0*v0 + v1*v1 + v2*v2;

    __shared__ float red[8];
    __shared__ float part[8][8];
    #pragma unroll
    for (int o = 16; o; o >>= 1) ss += __shfl_down_sync(0xffffffffu, ss, o);
    if ((t & 31) == 0) red[t >> 5] = ss;
    __syncthreads();
    if (t < 8) {
        ss = red[t];
        #pragma unroll
        for (int o = 4; o; o >>= 1) ss += __shfl_down_sync(0xffu, ss, o);
        if (t == 0) red[0] = ss;
    }
    __syncthreads();
    float inv = rsqrtf(red[0] * (1.0f/DM) + 1e-5f);
    float o0 = v0*inv*w[t], o1 = v1*inv*w[t+256], o2 = v2*inv*w[t+512];
    out[t] = o0; out[t+256] = o1; out[t+512] = o2;

    if (WHICH == 1) {
        float d[8];
        #pragma unroll
        for (int e = 0; e < 8; e++)
            d[e] = o0*gw[e*DM + t] + o1*gw[e*DM + t + 256] + o2*gw[e*DM + t + 512];
        #pragma unroll
        for (int e = 0; e < 8; e++) {
            #pragma unroll
            for (int o = 16; o; o >>= 1) d[e] += __shfl_down_sync(0xffffffffu, d[e], o);
        }
        if ((t & 31) == 0) {
            #pragma unroll
            for (int e = 0; e < 8; e++) part[t >> 5][e] = d[e];
        }
        __syncthreads();
        if (t < 8) {
            float l = 0.f;
            #pragma unroll
            for (int wv = 0; wv < 8; wv++) l += part[wv][t];
            g_logits[n*NE + t] = l;
        }
    }
}

// ---------------- top-2 of softmax ----------------
__global__ void __launch_bounds__(128) top2_kernel()
{
    int n = blockIdx.x * 128 + threadIdx.x;
    if (n >= SQ) return;
    float lg[NE];
    #pragma unroll
    for (int i = 0; i < NE; i++) lg[i] = g_logits[n*NE + i];
    float m = -1e30f;
    #pragma unroll
    for (int i = 0; i < NE; i++) m = fmaxf(m, lg[i]);
    float s = 0.f;
    #pragma unroll
    for (int i = 0; i < NE; i++) { lg[i] = expf(lg[i] - m); s += lg[i]; }
    float invs = 1.f / s;
    int e0 = -1, e1 = -1; float v0 = -1.f, v1 = -1.f;
    #pragma unroll
    for (int i = 0; i < NE; i++) {
        float v = lg[i] * invs;
        if (v > v0) { v1 = v0; e1 = e0; v0 = v; e0 = i; }
        else if (v > v1) { v1 = v; e1 = i; }
    }
    g_idx[2*n]     = e0;
    g_idx[2*n + 1] = e1;
    g_wts[2*n]     = fmaxf(v0, 1e-7f);
    g_wts[2*n + 1] = fmaxf(v1, 1e-7f);
}

// ---------------- attention: tf32 mma + fast exp ----------------
__global__ void __launch_bounds__(256) attn_mma_kernel(const float* __restrict__ x)
{
    int q0 = blockIdx.x * 64;
    int h  = blockIdx.y;

    extern __shared__ __align__(16) uint32_t sm[];
    uint32_t* Qs = sm;
    uint32_t* Ks = sm + 4096;
    uint32_t* Vt = sm + 8192;
    uint32_t* Ps = sm + 12288;
    float* rssm  = (float*)(sm + 16384);

    int tid = threadIdx.x, lane = tid & 31, wid = tid >> 5;
    int wm = wid & 3, wn = wid >> 2, gid = lane >> 2, qid = lane & 3;

    {
        int r = tid >> 2, c4 = (tid & 3) * 16;
        const float* src = g_xn + (size_t)(q0 + r)*DM + h*HD + c4;
        #pragma unroll
        for (int j = 0; j < 4; j++) {
            float4 v = *(const float4*)(src + 4*j);
            uint32_t c = (uint32_t)((c4 + 4*j) ^ ((r & 7) << 2));
            uint4 u = make_uint4(tf32c(v.x), tf32c(v.y), tf32c(v.z), tf32c(v.w));
            *(uint4*)&Qs[r*64 + c] = u;
        }
    }

    float acc_o[4][4] = {};
    float rs0 = 0.f, rs1 = 0.f;
    int r0 = wm*16 + gid;

    for (int kt = 0; kt < SQ/64; kt++) {
        __syncthreads();
        {
            int r = tid >> 2, c4 = (tid & 3) * 16;
            const float* src = g_xn + (size_t)(kt*64 + r)*DM + h*HD + c4;
            #pragma unroll
            for (int j = 0; j < 4; j++) {
                float4 v = *(const float4*)(src + 4*j);
                int d0 = c4 + 4*j;
                uint4 u = make_uint4(tf32c(v.x), tf32c(v.y), tf32c(v.z), tf32c(v.w));
                *(uint4*)&Ks[r*64 + (d0 ^ ((r & 7) << 2))] = u;
                Vt[(d0+0)*64 + (r ^ (((d0+0) & 7) << 2))] = u.x;
                Vt[(d0+1)*64 + (r ^ (((d0+1) & 7) << 2))] = u.y;
                Vt[(d0+2)*64 + (r ^ (((d0+2) & 7) << 2))] = u.z;
                Vt[(d0+3)*64 + (r ^ (((d0+3) & 7) << 2))] = u.w;
            }
        }
        __syncthreads();

        float acc_s[4][4] = {};
        #pragma unroll
        for (int kk = 0; kk < 8; kk++) {
            int kb = kk * 8;
            uint32_t af[4];
            af[0] = lds64(Qs, r0,     kb + qid);
            af[1] = lds64(Qs, r0 + 8, kb + qid);
            af[2] = lds64(Qs, r0,     kb + qid + 4);
            af[3] = lds64(Qs, r0 + 8, kb + qid + 4);
            #pragma unroll
            for (int ni = 0; ni < 4; ni++) {
                uint32_t bf[2];
                int n = wn*32 + 8*ni + gid;
                bf[0] = lds64(Ks, n, kb + qid);
                bf[1] = lds64(Ks, n, kb + qid + 4);
                mma8(acc_s[ni], af, bf);
            }
        }

        float p0 = 0.f, p1 = 0.f;
        #pragma unroll
        for (int ni = 0; ni < 4; ni++) {
            float e0 = fexps(acc_s[ni][0]);
            float e1 = fexps(acc_s[ni][1]);
            float e2 = fexps(acc_s[ni][2]);
            float e3 = fexps(acc_s[ni][3]);
            p0 += e0 + e1;
            p1 += e2 + e3;
            int col = wn*32 + 8*ni + 2*qid;
            uint2 u0 = make_uint2(tf32c(e0), tf32c(e1));
            uint2 u1 = make_uint2(tf32c(e2), tf32c(e3));
            *(uint2*)&Ps[r0*64 + (col ^ ((r0 & 7) << 2))] = u0;
            int r1 = r0 + 8;
            *(uint2*)&Ps[r1*64 + (col ^ ((r1 & 7) << 2))] = u1;
        }
        p0 += __shfl_xor_sync(0xffffffffu, p0, 1);
        p0 += __shfl_xor_sync(0xffffffffu, p0, 2);
        p1 += __shfl_xor_sync(0xffffffffu, p1, 1);
        p1 += __shfl_xor_sync(0xffffffffu, p1, 2);
        rs0 += p0; rs1 += p1;
        __syncthreads();

        #pragma unroll
        for (int kk = 0; kk < 8; kk++) {
            int kb = kk * 8;
            uint32_t af[4];
            af[0] = lds64(Ps, r0,     kb + qid);
            af[1] = lds64(Ps, r0 + 8, kb + qid);
            af[2] = lds64(Ps, r0,     kb + qid + 4);
            af[3] = lds64(Ps, r0 + 8, kb + qid + 4);
            #pragma unroll
            for (int ni = 0; ni < 4; ni++) {
                uint32_t bf[2];
                int n = wn*32 + 8*ni + gid;
                bf[0] = lds64(Vt, n, kb + qid);
                bf[1] = lds64(Vt, n, kb + qid + 4);
                mma8(acc_o[ni], af, bf);
            }
        }
    }

    if (qid == 0) {
        rssm[wn*64 + r0]     = rs0;
        rssm[wn*64 + r0 + 8] = rs1;
    }
    __syncthreads();
    float inv0 = 1.f / (rssm[r0]     + rssm[64 + r0]);
    float inv1 = 1.f / (rssm[r0 + 8] + rssm[64 + r0 + 8]);

    #pragma unroll
    for (int ni = 0; ni < 4; ni++) {
        int col = h*HD + wn*32 + 8*ni + 2*qid;
        size_t gi0 = (size_t)(q0 + r0)*DM + col;
        size_t gi1 = (size_t)(q0 + r0 + 8)*DM + col;
        float2 x0 = *(const float2*)&x[gi0];
        float2 x1 = *(const float2*)&x[gi1];
        float2 o0 = make_float2(x0.x + acc_o[ni][0]*inv0, x0.y + acc_o[ni][1]*inv0);
        float2 o1 = make_float2(x1.x + acc_o[ni][2]*inv1, x1.y + acc_o[ni][3]*inv1);
        *(float2*)&g_res[gi0] = o0;
        *(float2*)&g_res[gi1] = o1;
    }
}

// ---------------- count + scan + scatter ----------------
__global__ void scan_kernel()
{
    __shared__ int cnt[NE];
    if (threadIdx.x < NE) { cnt[threadIdx.x] = 0; g_fill[threadIdx.x] = 0; }
    __syncthreads();
    for (int i = threadIdx.x; i < NSLOT; i += 256) atomicAdd(&cnt[g_idx[i]], 1);
    __syncthreads();
    if (threadIdx.x == 0) {
        int off = 0;
        for (int e = 0; e < NE; e++) { g_counts[e] = cnt[e]; g_offsets[e] = off; off += cnt[e]; }
    }
}

__global__ void scatter_kernel()
{
    int i = blockIdx.x * 256 + threadIdx.x;
    if (i >= NSLOT) return;
    int e = g_idx[i];
    int p = atomicAdd(&g_fill[e], 1);
    g_list[g_offsets[e] + p] = i;
}

// ---------------- h = silu(a) * g ----------------
__global__ void silu_mul_kernel()
{
    int i = (blockIdx.x * 256 + threadIdx.x) * 4;
    float4 a = *(float4*)&g_a[i];
    float4 g = *(float4*)&g_gv[i];
    float4 o;
    o.x = fsilu(a.x) * g.x;
    o.y = fsilu(a.y) * g.y;
    o.z = fsilu(a.z) * g.z;
    o.w = fsilu(a.w) * g.w;
    *(float4*)&g_h[i] = o;
}

// ---------------- tf32 mma GEMM, cp.async 3-stage: C = A * B^T ----------------
template<int MODE>
__global__ void __launch_bounds__(256, 2) mma_gemm(const float* __restrict__ Bw,
                                                   const float* __restrict__ Bw2,
                                                   float* __restrict__ Cout,
                                                   const float* __restrict__ bias,
                                                   const float* __restrict__ bias2)
{
    constexpr int KD = (MODE==1) ? ISH : (MODE==3 ? NI : DM);
    constexpr int NC = KD / 32;
    constexpr int NN = (MODE==0) ? ISH : (MODE==2 ? NI : DM);

    int bx = blockIdx.x;
    int tgt = 0;
    const float* Bsel = Bw;
    const float* bsel = bias;
    if (MODE == 2 && bx >= NI/128) { tgt = 1; bx -= NI/128; Bsel = Bw2; bsel = bias2; }
    int n0 = bx * 128;
    int m0 = blockIdx.y * 128;
    int M = SQ, moff = 0;

    if (MODE >= 2) {
        int e = blockIdx.z;
        int cnt = g_counts[e];
        if (m0 >= cnt) return;
        M = cnt; moff = g_offsets[e];
        Bsel += (size_t)e * NN * KD;
        bsel += (size_t)e * NN;
    }

    extern __shared__ __align__(128) uint32_t smu[];
    uint32_t smbase = smem_u32(smu);

    int tid = threadIdx.x, lane = tid & 31, wid = tid >> 5;
    int wm = wid & 3, wn = wid >> 2;
    int gid = lane >> 2, qid = lane & 3;

    int r  = tid >> 1;
    int hf = tid & 1;
    int mrow = m0 + r; if (mrow > M - 1) mrow = M - 1;
    const float* arow;
    if      (MODE == 2) arow = g_xf + (size_t)(g_list[moff + mrow] >> 1) * DM;
    else if (MODE == 3) arow = g_h  + (size_t)(moff + mrow) * NI;
    else if (MODE == 1) arow = g_t  + (size_t)mrow * ISH;
    else                arow = g_xf + (size_t)mrow * DM;
    const float* brow = Bsel + (size_t)(n0 + r) * KD;

    uint32_t sb[4];
    #pragma unroll
    for (int i = 0; i < 4; i++) {
        int k0 = hf*16 + i*4;
        sb[i] = (uint32_t)(r*128 + 4*(k0 ^ ((r & 7) << 2)));
    }
    const int ks0 = hf * 16;

#define ISSUE_CHUNK(KC) do { \
        int _kc = (KC); \
        int _st = _kc % 3; \
        uint32_t _da = smbase + (uint32_t)_st * 16384u; \
        uint32_t _db = smbase + 49152u + (uint32_t)_st * 16384u; \
        const float* _as = arow + _kc*32 + ks0; \
        const float* _bs = brow + _kc*32 + ks0; \
        cpasync16(_da + sb[0], _as);      cpasync16(_db + sb[0], _bs); \
        cpasync16(_da + sb[1], _as + 4);  cpasync16(_db + sb[1], _bs + 4); \
        cpasync16(_da + sb[2], _as + 8);  cpasync16(_db + sb[2], _bs + 8); \
        cpasync16(_da + sb[3], _as + 12); cpasync16(_db + sb[3], _bs + 12); \
        CP_COMMIT(); \
    } while (0)

    ISSUE_CHUNK(0);
    ISSUE_CHUNK(1);

    float acc[2][8][4] = {};

    for (int kc = 0; kc < NC; kc++) {
        if (kc == NC - 1) { asm volatile("cp.async.wait_group 0;" ::: "memory"); }
        else              { asm volatile("cp.async.wait_group 1;" ::: "memory"); }
        __syncthreads();
        if (kc + 2 < NC) ISSUE_CHUNK(kc + 2);

        int st = kc % 3;
        const uint32_t* cA = smu + st * 4096;
        const uint32_t* cB = smu + 12288 + st * 4096;
        #pragma unroll
        for (int kk = 0; kk < 4; kk++) {
            int kb = kk * 8;
            uint32_t af[2][4], bf[8][2];
            #pragma unroll
            for (int mi = 0; mi < 2; mi++) {
                int rr = 32*wm + 16*mi + gid;
                af[mi][0] = ldsm(cA, rr,     kb + qid);
                af[mi][1] = ldsm(cA, rr + 8, kb + qid);
                af[mi][2] = ldsm(cA, rr,     kb + qid + 4);
                af[mi][3] = ldsm(cA, rr + 8, kb + qid + 4);
            }
            #pragma unroll
            for (int ni = 0; ni < 8; ni++) {
                int n = 64*wn + 8*ni + gid;
                bf[ni][0] = ldsm(cB, n, kb + qid);
                bf[ni][1] = ldsm(cB, n, kb + qid + 4);
            }
            #pragma unroll
            for (int mi = 0; mi < 2; mi++)
                #pragma unroll
                for (int ni = 0; ni < 8; ni++)
                    mma8(acc[mi][ni], af[mi], bf[ni]);
        }
    }
#undef ISSUE_CHUNK

    #pragma unroll
    for (int mi = 0; mi < 2; mi++) {
        #pragma unroll
        for (int half = 0; half < 2; half++) {
            int row = m0 + 32*wm + 16*mi + gid + 8*half;
            if (MODE >= 2 && row >= M) continue;
            #pragma unroll
            for (int ni = 0; ni < 8; ni++) {
                float v0 = acc[mi][ni][2*half + 0];
                float v1 = acc[mi][ni][2*half + 1];
                int col = n0 + 64*wn + 8*ni + 2*qid;
                float b0 = bsel[col], b1 = bsel[col + 1];
                if (MODE == 0) {
                    float2 o = make_float2(fsilu(v0 + b0), fsilu(v1 + b1));
                    *(float2*)&g_t[(size_t)row*ISH + col] = o;
                } else if (MODE == 1) {
                    float2 rr = *(const float2*)&g_res[(size_t)row*DM + col];
                    float2 a0 = *(const float2*)&g_yk[(size_t)(2*row)*DM + col];
                    float2 a1 = *(const float2*)&g_yk[(size_t)(2*row + 1)*DM + col];
                    float2 o  = make_float2(v0 + b0 + rr.x + a0.x + a1.x,
                                            v1 + b1 + rr.y + a0.y + a1.y);
                    *(float2*)&Cout[(size_t)row*DM + col] = o;
                } else if (MODE == 2) {
                    float* dst = (tgt ? g_gv : g_a) + (size_t)(moff + row)*NI + col;
                    *(float2*)dst = make_float2(v0 + b0, v1 + b1);
                } else {
                    int code = g_list[moff + row];
                    float w = g_wts[code];
                    float2 o = make_float2(w*(v0 + b0), w*(v1 + b1));
                    *(float2*)&g_yk[(size_t)code*DM + col] = o;
                }
            }
        }
    }
}

// ---------------- launch ----------------
extern "C" void kernel_launch(void* const* d_in, const int* in_sizes, int n_in,
                              void* d_out, int out_size)
{
    const float* x       = (const float*)d_in[0];
    const float* norm1_w = (const float*)d_in[1];
    const float* norm3_w = (const float*)d_in[2];
    const float* gate_w  = (const float*)d_in[3];
    const float* w1      = (const float*)d_in[4];
    const float* b1      = (const float*)d_in[5];
    const float* w2      = (const float*)d_in[6];
    const float* b2      = (const float*)d_in[7];
    const float* w3      = (const float*)d_in[8];
    const float* b3      = (const float*)d_in[9];
    const float* fc1_w   = (const float*)d_in[10];
    const float* fc1_b   = (const float*)d_in[11];
    const float* fc2_w   = (const float*)d_in[12];
    const float* fc2_b   = (const float*)d_in[13];
    float* out = (float*)d_out;

    const int SMG = 98304;
    const int SMA = 16384*4 + 512;
    static bool attr_done = false;
    if (!attr_done) {
        cudaFuncSetAttribute(mma_gemm<0>, cudaFuncAttributeMaxDynamicSharedMemorySize, SMG);
        cudaFuncSetAttribute(mma_gemm<1>, cudaFuncAttributeMaxDynamicSharedMemorySize, SMG);
        cudaFuncSetAttribute(mma_gemm<2>, cudaFuncAttributeMaxDynamicSharedMemorySize, SMG);
        cudaFuncSetAttribute(mma_gemm<3>, cudaFuncAttributeMaxDynamicSharedMemorySize, SMG);
        cudaFuncSetAttribute(attn_mma_kernel, cudaFuncAttributeMaxDynamicSharedMemorySize, SMA);
        attr_done = true;
    }

    rmsnorm_kernel<0><<<SQ, 256>>>(x, norm1_w, nullptr);
    attn_mma_kernel<<<dim3(SQ/64, NH), 256, SMA>>>(x);
    rmsnorm_kernel<1><<<SQ, 256>>>(nullptr, norm3_w, gate_w);
    top2_kernel<<<SQ/128, 128>>>();
    scan_kernel<<<1, 256>>>();
    scatter_kernel<<<NSLOT/256, 256>>>();

    mma_gemm<2><<<dim3(2*NI/128, 32, NE), 256, SMG>>>(w1, w3, nullptr, b1, b3);
    silu_mul_kernel<<<(NSLOT*NI)/1024, 256>>>();
    mma_gemm<3><<<dim3(DM/128, 32, NE), 256, SMG>>>(w2, nullptr, nullptr, b2, nullptr);
    mma_gemm<0><<<dim3(ISH/128, SQ/128), 256, SMG>>>(fc1_w, nullptr, nullptr, fc1_b, nullptr);
    mma_gemm<1><<<dim3(DM/128, SQ/128), 256, SMG>>>(fc2_w, nullptr, out, fc2_b, nullptr);
}

// round 6
// speedup vs baseline: 2.4609x; 1.2297x over previous
#include <cuda_runtime.h>
#include <math.h>
#include <stdint.h>

#define SQ   2048
#define DM   768
#define NH   12
#define HD   64
#define NE   8
#define NI   1024
#define ISH  2048
#define NSLOT (2*SQ)

// ---------------- device scratch ----------------
__device__ __align__(16) float g_xn [SQ*DM];
__device__ __align__(16) float g_res[SQ*DM];
__device__ __align__(16) float g_xf [SQ*DM];
__device__ __align__(16) float g_t  [SQ*ISH];
__device__ __align__(16) float g_a  [NSLOT*NI];
__device__ __align__(16) float g_gv [NSLOT*NI];
__device__ __align__(16) float g_h  [NSLOT*NI];
__device__ __align__(16) float g_yk [NSLOT*DM];
__device__ float g_logits[SQ*NE];
__device__ float g_wts[NSLOT];
__device__ int   g_counts[NE];
__device__ int   g_offsets[NE];
__device__ int   g_list[NSLOT];

// ---------------- helpers ----------------
__device__ __forceinline__ uint32_t smem_u32(const void* p){
    uint32_t a;
    asm("{ .reg .u64 t; cvta.to.shared.u64 t, %1; cvt.u32.u64 %0, t; }" : "=r"(a) : "l"(p));
    return a;
}
__device__ __forceinline__ uint32_t tf32c(float f){
    uint32_t u; asm("cvt.rna.tf32.f32 %0, %1;" : "=r"(u) : "f"(f)); return u;
}
__device__ __forceinline__ void mma8(float* d, const uint32_t* a, const uint32_t* b){
    asm volatile("mma.sync.aligned.m16n8k8.row.col.f32.tf32.tf32.f32 "
        "{%0,%1,%2,%3}, {%4,%5,%6,%7}, {%8,%9}, {%0,%1,%2,%3};"
        : "+f"(d[0]), "+f"(d[1]), "+f"(d[2]), "+f"(d[3])
        : "r"(a[0]), "r"(a[1]), "r"(a[2]), "r"(a[3]), "r"(b[0]), "r"(b[1]));
}
__device__ __forceinline__ uint32_t ldsm(const uint32_t* base, int row, int k){
    return base[row*32 + (k ^ ((row & 7) << 2))];
}
__device__ __forceinline__ uint32_t lds64(const uint32_t* base, int r, int c){
    return base[r*64 + (c ^ ((r & 7) << 2))];
}
__device__ __forceinline__ void cpasync16(uint32_t dst, const void* src){
    asm volatile("cp.async.cg.shared.global [%0], [%1], 16;" :: "r"(dst), "l"(src) : "memory");
}
#define CP_COMMIT() asm volatile("cp.async.commit_group;" ::: "memory")

__device__ __forceinline__ float fexp2n(float y){
    y = fminf(fmaxf(y, -126.f), 126.f);
    float r = y + 12582912.f;
    float f = y - (r - 12582912.f);
    float p = 1.3333558146e-3f;
    p = fmaf(p, f, 9.6181291776e-3f);
    p = fmaf(p, f, 5.5504108664e-2f);
    p = fmaf(p, f, 2.4022650696e-1f);
    p = fmaf(p, f, 6.9314718056e-1f);
    p = fmaf(p, f, 1.0f);
    return __int_as_float(__float_as_int(p) + (__float_as_int(r) << 23));
}
__device__ __forceinline__ float fexps(float s){ return fexp2n(s * 0.18033688011112042f); }
__device__ __forceinline__ float frcp(float x){
    float y = __int_as_float(0x7EF311C3 - __float_as_int(x));
    y = y * (2.f - x*y);
    y = y * (2.f - x*y);
    y = y * (2.f - x*y);
    return y;
}
__device__ __forceinline__ float fsilu(float a){
    float t = fexp2n(-a * 1.4426950408889634f);
    return a * frcp(1.f + t);
}

// ---------------- rmsnorm (WHICH=1 also emits gate logits) ----------------
template<int WHICH>
__global__ void __launch_bounds__(256) rmsnorm_kernel(const float* __restrict__ x,
                                                      const float* __restrict__ w,
                                                      const float* __restrict__ gw)
{
    int n = blockIdx.x;
    int t = threadIdx.x;
    const float* row = (WHICH == 0) ? (x + (size_t)n*DM) : (g_res + (size_t)n*DM);
    float* out = (WHICH == 0) ? (g_xn + (size_t)n*DM) : (g_xf + (size_t)n*DM);

    float v0 = row[t], v1 = row[t+256], v2 = row[t+512];
    float ss = v0*v0 + v1*v1 + v2*v2;

    __shared__ float red[8];
    __shared__ float part[8][8];
    #pragma unroll
    for (int o = 16; o; o >>= 1) ss += __shfl_down_sync(0xffffffffu, ss, o);
    if ((t & 31) == 0) red[t >> 5] = ss;
    __syncthreads();
    if (t < 8) {
        ss = red[t];
        #pragma unroll
        for (int o = 4; o; o >>= 1) ss += __shfl_down_sync(0xffu, ss, o);
        if (t == 0) red[0] = ss;
    }
    __syncthreads();
    float inv = rsqrtf(red[0] * (1.0f/DM) + 1e-5f);
    float o0 = v0*inv*w[t], o1 = v1*inv*w[t+256], o2 = v2*inv*w[t+512];
    out[t] = o0; out[t+256] = o1; out[t+512] = o2;

    if (WHICH == 1) {
        float d[8];
        #pragma unroll
        for (int e = 0; e < 8; e++)
            d[e] = o0*gw[e*DM + t] + o1*gw[e*DM + t + 256] + o2*gw[e*DM + t + 512];
        #pragma unroll
        for (int e = 0; e < 8; e++) {
            #pragma unroll
            for (int o = 16; o; o >>= 1) d[e] += __shfl_down_sync(0xffffffffu, d[e], o);
        }
        if ((t & 31) == 0) {
            #pragma unroll
            for (int e = 0; e < 8; e++) part[t >> 5][e] = d[e];
        }
        __syncthreads();
        if (t < 8) {
            float l = 0.f;
            #pragma unroll
            for (int wv = 0; wv < 8; wv++) l += part[wv][t];
            g_logits[n*NE + t] = l;
        }
    }
}

// ---------------- merged routing: top2 + count + scan + scatter (1 block) ----------------
__global__ void __launch_bounds__(1024) route_kernel()
{
    __shared__ int cnt[NE], off[NE], fill[NE];
    int t = threadIdx.x;
    if (t < NE) { cnt[t] = 0; fill[t] = 0; }
    __syncthreads();

    int eidx[2][2];
    #pragma unroll
    for (int j = 0; j < 2; j++) {
        int n = t*2 + j;
        float lg[NE];
        #pragma unroll
        for (int i = 0; i < NE; i++) lg[i] = g_logits[n*NE + i];
        float m = -1e30f;
        #pragma unroll
        for (int i = 0; i < NE; i++) m = fmaxf(m, lg[i]);
        float s = 0.f;
        #pragma unroll
        for (int i = 0; i < NE; i++) { lg[i] = fexp2n((lg[i] - m) * 1.4426950408889634f); s += lg[i]; }
        float invs = 1.f / s;
        int e0 = -1, e1 = -1; float v0 = -1.f, v1 = -1.f;
        #pragma unroll
        for (int i = 0; i < NE; i++) {
            float v = lg[i] * invs;
            if (v > v0) { v1 = v0; e1 = e0; v0 = v; e0 = i; }
            else if (v > v1) { v1 = v; e1 = i; }
        }
        g_wts[2*n]     = fmaxf(v0, 1e-7f);
        g_wts[2*n + 1] = fmaxf(v1, 1e-7f);
        eidx[j][0] = e0; eidx[j][1] = e1;
        atomicAdd(&cnt[e0], 1);
        atomicAdd(&cnt[e1], 1);
    }
    __syncthreads();
    if (t == 0) {
        int o = 0;
        for (int e = 0; e < NE; e++) { g_counts[e] = cnt[e]; off[e] = o; g_offsets[e] = o; o += cnt[e]; }
    }
    __syncthreads();
    #pragma unroll
    for (int j = 0; j < 2; j++) {
        #pragma unroll
        for (int k = 0; k < 2; k++) {
            int e = eidx[j][k];
            int p = atomicAdd(&fill[e], 1);
            g_list[off[e] + p] = (t*2 + j)*2 + k;
        }
    }
}

// ---------------- attention: tf32 mma + fast exp ----------------
__global__ void __launch_bounds__(256) attn_mma_kernel(const float* __restrict__ x)
{
    int q0 = blockIdx.x * 64;
    int h  = blockIdx.y;

    extern __shared__ __align__(16) uint32_t sm[];
    uint32_t* Qs = sm;
    uint32_t* Ks = sm + 4096;
    uint32_t* Vt = sm + 8192;
    uint32_t* Ps = sm + 12288;
    float* rssm  = (float*)(sm + 16384);

    int tid = threadIdx.x, lane = tid & 31, wid = tid >> 5;
    int wm = wid & 3, wn = wid >> 2, gid = lane >> 2, qid = lane & 3;

    {
        int r = tid >> 2, c4 = (tid & 3) * 16;
        const float* src = g_xn + (size_t)(q0 + r)*DM + h*HD + c4;
        #pragma unroll
        for (int j = 0; j < 4; j++) {
            float4 v = *(const float4*)(src + 4*j);
            uint32_t c = (uint32_t)((c4 + 4*j) ^ ((r & 7) << 2));
            uint4 u = make_uint4(tf32c(v.x), tf32c(v.y), tf32c(v.z), tf32c(v.w));
            *(uint4*)&Qs[r*64 + c] = u;
        }
    }

    float acc_o[4][4] = {};
    float rs0 = 0.f, rs1 = 0.f;
    int r0 = wm*16 + gid;

    for (int kt = 0; kt < SQ/64; kt++) {
        __syncthreads();
        {
            int r = tid >> 2, c4 = (tid & 3) * 16;
            const float* src = g_xn + (size_t)(kt*64 + r)*DM + h*HD + c4;
            #pragma unroll
            for (int j = 0; j < 4; j++) {
                float4 v = *(const float4*)(src + 4*j);
                int d0 = c4 + 4*j;
                uint4 u = make_uint4(tf32c(v.x), tf32c(v.y), tf32c(v.z), tf32c(v.w));
                *(uint4*)&Ks[r*64 + (d0 ^ ((r & 7) << 2))] = u;
                Vt[(d0+0)*64 + (r ^ (((d0+0) & 7) << 2))] = u.x;
                Vt[(d0+1)*64 + (r ^ (((d0+1) & 7) << 2))] = u.y;
                Vt[(d0+2)*64 + (r ^ (((d0+2) & 7) << 2))] = u.z;
                Vt[(d0+3)*64 + (r ^ (((d0+3) & 7) << 2))] = u.w;
            }
        }
        __syncthreads();

        float acc_s[4][4] = {};
        #pragma unroll
        for (int kk = 0; kk < 8; kk++) {
            int kb = kk * 8;
            uint32_t af[4];
            af[0] = lds64(Qs, r0,     kb + qid);
            af[1] = lds64(Qs, r0 + 8, kb + qid);
            af[2] = lds64(Qs, r0,     kb + qid + 4);
            af[3] = lds64(Qs, r0 + 8, kb + qid + 4);
            #pragma unroll
            for (int ni = 0; ni < 4; ni++) {
                uint32_t bf[2];
                int n = wn*32 + 8*ni + gid;
                bf[0] = lds64(Ks, n, kb + qid);
                bf[1] = lds64(Ks, n, kb + qid + 4);
                mma8(acc_s[ni], af, bf);
            }
        }

        float p0 = 0.f, p1 = 0.f;
        #pragma unroll
        for (int ni = 0; ni < 4; ni++) {
            float e0 = fexps(acc_s[ni][0]);
            float e1 = fexps(acc_s[ni][1]);
            float e2 = fexps(acc_s[ni][2]);
            float e3 = fexps(acc_s[ni][3]);
            p0 += e0 + e1;
            p1 += e2 + e3;
            int col = wn*32 + 8*ni + 2*qid;
            uint2 u0 = make_uint2(tf32c(e0), tf32c(e1));
            uint2 u1 = make_uint2(tf32c(e2), tf32c(e3));
            *(uint2*)&Ps[r0*64 + (col ^ ((r0 & 7) << 2))] = u0;
            int r1 = r0 + 8;
            *(uint2*)&Ps[r1*64 + (col ^ ((r1 & 7) << 2))] = u1;
        }
        p0 += __shfl_xor_sync(0xffffffffu, p0, 1);
        p0 += __shfl_xor_sync(0xffffffffu, p0, 2);
        p1 += __shfl_xor_sync(0xffffffffu, p1, 1);
        p1 += __shfl_xor_sync(0xffffffffu, p1, 2);
        rs0 += p0; rs1 += p1;
        __syncthreads();

        #pragma unroll
        for (int kk = 0; kk < 8; kk++) {
            int kb = kk * 8;
            uint32_t af[4];
            af[0] = lds64(Ps, r0,     kb + qid);
            af[1] = lds64(Ps, r0 + 8, kb + qid);
            af[2] = lds64(Ps, r0,     kb + qid + 4);
            af[3] = lds64(Ps, r0 + 8, kb + qid + 4);
            #pragma unroll
            for (int ni = 0; ni < 4; ni++) {
                uint32_t bf[2];
                int n = wn*32 + 8*ni + gid;
                bf[0] = lds64(Vt, n, kb + qid);
                bf[1] = lds64(Vt, n, kb + qid + 4);
                mma8(acc_o[ni], af, bf);
            }
        }
    }

    if (qid == 0) {
        rssm[wn*64 + r0]     = rs0;
        rssm[wn*64 + r0 + 8] = rs1;
    }
    __syncthreads();
    float inv0 = 1.f / (rssm[r0]     + rssm[64 + r0]);
    float inv1 = 1.f / (rssm[r0 + 8] + rssm[64 + r0 + 8]);

    #pragma unroll
    for (int ni = 0; ni < 4; ni++) {
        int col = h*HD + wn*32 + 8*ni + 2*qid;
        size_t gi0 = (size_t)(q0 + r0)*DM + col;
        size_t gi1 = (size_t)(q0 + r0 + 8)*DM + col;
        float2 x0 = *(const float2*)&x[gi0];
        float2 x1 = *(const float2*)&x[gi1];
        float2 o0 = make_float2(x0.x + acc_o[ni][0]*inv0, x0.y + acc_o[ni][1]*inv0);
        float2 o1 = make_float2(x1.x + acc_o[ni][2]*inv1, x1.y + acc_o[ni][3]*inv1);
        *(float2*)&g_res[gi0] = o0;
        *(float2*)&g_res[gi1] = o1;
    }
}

// ---------------- h = silu(a) * g ----------------
__global__ void silu_mul_kernel()
{
    int i = (blockIdx.x * 256 + threadIdx.x) * 4;
    float4 a = *(float4*)&g_a[i];
    float4 g = *(float4*)&g_gv[i];
    float4 o;
    o.x = fsilu(a.x) * g.x;
    o.y = fsilu(a.y) * g.y;
    o.z = fsilu(a.z) * g.z;
    o.w = fsilu(a.w) * g.w;
    *(float4*)&g_h[i] = o;
}

// ---------------- tf32 mma GEMM, cp.async 3-stage, tile BM x 128 ----------------
// MODE 0: fc1 : A=g_xf          B=fc1_w     -> g_t       silu(acc+bias)
// MODE 1: fc2 : A=g_t           B=fc2_w     -> out       acc+bias+res+yk0+yk1
// MODE 2: up  : A=g_xf (gather) B=w1/w3[e]  -> g_a/g_gv  acc+bias
// MODE 3: dn  : A=g_h (compact) B=w2[e]     -> g_yk      wts*(acc+bias) scatter
template<int MODE, int BM>
__global__ void __launch_bounds__(256, 2) mma_gemm(const float* __restrict__ Bw,
                                                   const float* __restrict__ Bw2,
                                                   float* __restrict__ Cout,
                                                   const float* __restrict__ bias,
                                                   const float* __restrict__ bias2)
{
    constexpr int KD  = (MODE==1) ? ISH : (MODE==3 ? NI : DM);
    constexpr int NC  = KD / 32;
    constexpr int NN  = (MODE==0) ? ISH : (MODE==2 ? NI : DM);
    constexpr int AW  = BM * 32;              // A stage words
    constexpr int BOFF = 3 * AW;              // B stages start (words)
    constexpr int WMN = (BM==128) ? 4 : 2;    // warps along m
    constexpr int NIT = (BM==128) ? 8 : 4;    // n-subtiles per warp
    constexpr int WNW = (BM==128) ? 64 : 32;  // warp n width

    int bx = blockIdx.x;
    int tgt = 0;
    const float* Bsel = Bw;
    const float* bsel = bias;
    if (MODE == 2 && bx >= NI/128) { tgt = 1; bx -= NI/128; Bsel = Bw2; bsel = bias2; }
    int n0 = bx * 128;
    int m0 = blockIdx.y * BM;
    int M = SQ, moff = 0;

    if (MODE >= 2) {
        int e = blockIdx.z;
        int cnt = g_counts[e];
        if (m0 >= cnt) return;
        M = cnt; moff = g_offsets[e];
        Bsel += (size_t)e * NN * KD;
        bsel += (size_t)e * NN;
    }

    extern __shared__ __align__(128) uint32_t smu[];
    uint32_t smbase = smem_u32(smu);

    int tid = threadIdx.x, lane = tid & 31, wid = tid >> 5;
    int wm = wid & (WMN-1), wn = wid / WMN;
    int gid = lane >> 2, qid = lane & 3;

    // A loader
    int ra, nka;            // row, number of k-offsets (cp16 each)
    int kofa[4];
    if (BM == 128) {
        ra = tid >> 1; nka = 4;
        int base = (tid & 1) * 16;
        kofa[0]=base; kofa[1]=base+4; kofa[2]=base+8; kofa[3]=base+12;
    } else {
        ra = tid >> 2; nka = 2;
        int base = (tid & 3) * 8;
        kofa[0]=base; kofa[1]=base+4; kofa[2]=0; kofa[3]=0;
    }
    int mrow = m0 + ra; if (mrow > M - 1) mrow = M - 1;
    const float* arow;
    if      (MODE == 2) arow = g_xf + (size_t)(g_list[moff + mrow] >> 1) * DM;
    else if (MODE == 3) arow = g_h  + (size_t)(moff + mrow) * NI;
    else if (MODE == 1) arow = g_t  + (size_t)mrow * ISH;
    else                arow = g_xf + (size_t)mrow * DM;

    uint32_t sba[4];
    #pragma unroll
    for (int i = 0; i < 4; i++)
        sba[i] = (uint32_t)(ra*128 + 4*(kofa[i] ^ ((ra & 7) << 2)));

    // B loader (always 128 rows x 32 k)
    int rb = tid >> 1;
    int kb0 = (tid & 1) * 16;
    const float* brow = Bsel + (size_t)(n0 + rb) * KD;
    uint32_t sbb[4];
    #pragma unroll
    for (int i = 0; i < 4; i++)
        sbb[i] = (uint32_t)(rb*128 + 4*((kb0 + 4*i) ^ ((rb & 7) << 2)));

#define ISSUE_CHUNK(KC) do { \
        int _kc = (KC); \
        int _st = _kc % 3; \
        uint32_t _da = smbase + (uint32_t)(_st * AW * 4); \
        uint32_t _db = smbase + (uint32_t)((BOFF + _st * 4096) * 4); \
        const float* _as = arow + _kc*32; \
        const float* _bs = brow + _kc*32 + kb0; \
        cpasync16(_da + sba[0], _as + kofa[0]); \
        cpasync16(_da + sba[1], _as + kofa[1]); \
        if (BM == 128) { \
            cpasync16(_da + sba[2], _as + kofa[2]); \
            cpasync16(_da + sba[3], _as + kofa[3]); \
        } \
        cpasync16(_db + sbb[0], _bs);      cpasync16(_db + sbb[1], _bs + 4); \
        cpasync16(_db + sbb[2], _bs + 8);  cpasync16(_db + sbb[3], _bs + 12); \
        CP_COMMIT(); \
    } while (0)

    ISSUE_CHUNK(0);
    ISSUE_CHUNK(1);

    float acc[2][NIT][4] = {};

    for (int kc = 0; kc < NC; kc++) {
        if (kc == NC - 1) { asm volatile("cp.async.wait_group 0;" ::: "memory"); }
        else              { asm volatile("cp.async.wait_group 1;" ::: "memory"); }
        __syncthreads();
        if (kc + 2 < NC) ISSUE_CHUNK(kc + 2);

        int st = kc % 3;
        const uint32_t* cA = smu + st * AW;
        const uint32_t* cB = smu + BOFF + st * 4096;
        #pragma unroll
        for (int kk = 0; kk < 4; kk++) {
            int kb = kk * 8;
            uint32_t af[2][4], bf[NIT][2];
            #pragma unroll
            for (int mi = 0; mi < 2; mi++) {
                int rr = 32*wm + 16*mi + gid;
                af[mi][0] = ldsm(cA, rr,     kb + qid);
                af[mi][1] = ldsm(cA, rr + 8, kb + qid);
                af[mi][2] = ldsm(cA, rr,     kb + qid + 4);
                af[mi][3] = ldsm(cA, rr + 8, kb + qid + 4);
            }
            #pragma unroll
            for (int ni = 0; ni < NIT; ni++) {
                int n = WNW*wn + 8*ni + gid;
                bf[ni][0] = ldsm(cB, n, kb + qid);
                bf[ni][1] = ldsm(cB, n, kb + qid + 4);
            }
            #pragma unroll
            for (int mi = 0; mi < 2; mi++)
                #pragma unroll
                for (int ni = 0; ni < NIT; ni++)
                    mma8(acc[mi][ni], af[mi], bf[ni]);
        }
    }
#undef ISSUE_CHUNK

    #pragma unroll
    for (int mi = 0; mi < 2; mi++) {
        #pragma unroll
        for (int half = 0; half < 2; half++) {
            int row = m0 + 32*wm + 16*mi + gid + 8*half;
            if (MODE >= 2 && row >= M) continue;
            #pragma unroll
            for (int ni = 0; ni < NIT; ni++) {
                float v0 = acc[mi][ni][2*half + 0];
                float v1 = acc[mi][ni][2*half + 1];
                int col = n0 + WNW*wn + 8*ni + 2*qid;
                float b0 = bsel[col], b1 = bsel[col + 1];
                if (MODE == 0) {
                    float2 o = make_float2(fsilu(v0 + b0), fsilu(v1 + b1));
                    *(float2*)&g_t[(size_t)row*ISH + col] = o;
                } else if (MODE == 1) {
                    float2 rr = *(const float2*)&g_res[(size_t)row*DM + col];
                    float2 a0 = *(const float2*)&g_yk[(size_t)(2*row)*DM + col];
                    float2 a1 = *(const float2*)&g_yk[(size_t)(2*row + 1)*DM + col];
                    float2 o  = make_float2(v0 + b0 + rr.x + a0.x + a1.x,
                                            v1 + b1 + rr.y + a0.y + a1.y);
                    *(float2*)&Cout[(size_t)row*DM + col] = o;
                } else if (MODE == 2) {
                    float* dst = (tgt ? g_gv : g_a) + (size_t)(moff + row)*NI + col;
                    *(float2*)dst = make_float2(v0 + b0, v1 + b1);
                } else {
                    int code = g_list[moff + row];
                    float w = g_wts[code];
                    float2 o = make_float2(w*(v0 + b0), w*(v1 + b1));
                    *(float2*)&g_yk[(size_t)code*DM + col] = o;
                }
            }
        }
    }
}

// ---------------- launch ----------------
extern "C" void kernel_launch(void* const* d_in, const int* in_sizes, int n_in,
                              void* d_out, int out_size)
{
    const float* x       = (const float*)d_in[0];
    const float* norm1_w = (const float*)d_in[1];
    const float* norm3_w = (const float*)d_in[2];
    const float* gate_w  = (const float*)d_in[3];
    const float* w1      = (const float*)d_in[4];
    const float* b1      = (const float*)d_in[5];
    const float* w2      = (const float*)d_in[6];
    const float* b2      = (const float*)d_in[7];
    const float* w3      = (const float*)d_in[8];
    const float* b3      = (const float*)d_in[9];
    const float* fc1_w   = (const float*)d_in[10];
    const float* fc1_b   = (const float*)d_in[11];
    const float* fc2_w   = (const float*)d_in[12];
    const float* fc2_b   = (const float*)d_in[13];
    float* out = (float*)d_out;

    const int SMG128 = 98304;   // 3*(16K A + 16K B)
    const int SMG64  = 73728;   // 3*(8K A + 16K B)
    const int SMA    = 16384*4 + 512;

    static cudaStream_t s2 = nullptr;
    static cudaEvent_t evA = nullptr, evB = nullptr;
    if (!s2) {
        cudaStreamCreateWithFlags(&s2, cudaStreamNonBlocking);
        cudaEventCreateWithFlags(&evA, cudaEventDisableTiming);
        cudaEventCreateWithFlags(&evB, cudaEventDisableTiming);
        cudaFuncSetAttribute((mma_gemm<0,128>), cudaFuncAttributeMaxDynamicSharedMemorySize, SMG128);
        cudaFuncSetAttribute((mma_gemm<1,64>),  cudaFuncAttributeMaxDynamicSharedMemorySize, SMG64);
        cudaFuncSetAttribute((mma_gemm<2,128>), cudaFuncAttributeMaxDynamicSharedMemorySize, SMG128);
        cudaFuncSetAttribute((mma_gemm<3,64>),  cudaFuncAttributeMaxDynamicSharedMemorySize, SMG64);
        cudaFuncSetAttribute(attn_mma_kernel,   cudaFuncAttributeMaxDynamicSharedMemorySize, SMA);
    }

    rmsnorm_kernel<0><<<SQ, 256>>>(x, norm1_w, nullptr);
    attn_mma_kernel<<<dim3(SQ/64, NH), 256, SMA>>>(x);
    rmsnorm_kernel<1><<<SQ, 256>>>(nullptr, norm3_w, gate_w);

    // fork: shared-expert fc1 on s2, concurrent with routing + expert chain
    cudaEventRecord(evA, 0);
    cudaStreamWaitEvent(s2, evA, 0);
    mma_gemm<0,128><<<dim3(ISH/128, SQ/128), 256, SMG128, s2>>>(fc1_w, nullptr, nullptr, fc1_b, nullptr);
    cudaEventRecord(evB, s2);

    route_kernel<<<1, 1024>>>();
    mma_gemm<2,128><<<dim3(2*NI/128, 32, NE), 256, SMG128>>>(w1, w3, nullptr, b1, b3);
    silu_mul_kernel<<<(NSLOT*NI)/1024, 256>>>();
    mma_gemm<3,64><<<dim3(DM/128, NSLOT/64, NE), 256, SMG64>>>(w2, nullptr, nullptr, b2, nullptr);

    // join: fc2 needs g_t (fc1) + g_yk (dn)
    cudaStreamWaitEvent(0, evB, 0);
    mma_gemm<1,64><<<dim3(DM/128, SQ/64), 256, SMG64>>>(fc2_w, nullptr, out, fc2_b, nullptr);
}

// round 8
// speedup vs baseline: 3.3822x; 1.3744x over previous
#include <cuda_runtime.h>
#include <cuda_fp16.h>
#include <math.h>
#include <stdint.h>

#define SQ   2048
#define DM   768
#define NH   12
#define HD   64
#define NE   8
#define NI   1024
#define ISH  2048
#define NSLOT (2*SQ)

// ---------------- device scratch ----------------
__device__ __align__(16) float g_xn [SQ*DM];
__device__ __align__(16) float g_res[SQ*DM];
__device__ __align__(16) __half g_xf[SQ*DM];
__device__ __align__(16) __half g_t [SQ*ISH];
__device__ __align__(16) float g_a  [NSLOT*NI];
__device__ __align__(16) float g_gv [NSLOT*NI];
__device__ __align__(16) __half g_h [NSLOT*NI];
__device__ __align__(16) float g_yk [NSLOT*DM];
__device__ float g_logits[SQ*NE];
__device__ float g_wts[NSLOT];
__device__ int   g_counts[NE];
__device__ int   g_offsets[NE];
__device__ int   g_list[NSLOT];
__device__ __align__(16) __half h_w1 [NE*NI*DM];
__device__ __align__(16) __half h_w3 [NE*NI*DM];
__device__ __align__(16) __half h_w2 [NE*DM*NI];
__device__ __align__(16) __half h_fc1[ISH*DM];
__device__ __align__(16) __half h_fc2[DM*ISH];

// ---------------- helpers ----------------
__device__ __forceinline__ uint32_t smem_u32(const void* p){
    uint32_t a;
    asm("{ .reg .u64 t; cvta.to.shared.u64 t, %1; cvt.u32.u64 %0, t; }" : "=r"(a) : "l"(p));
    return a;
}
__device__ __forceinline__ uint32_t tf32c(float f){
    uint32_t u; asm("cvt.rna.tf32.f32 %0, %1;" : "=r"(u) : "f"(f)); return u;
}
__device__ __forceinline__ void mma8(float* d, const uint32_t* a, const uint32_t* b){
    asm volatile("mma.sync.aligned.m16n8k8.row.col.f32.tf32.tf32.f32 "
        "{%0,%1,%2,%3}, {%4,%5,%6,%7}, {%8,%9}, {%0,%1,%2,%3};"
        : "+f"(d[0]), "+f"(d[1]), "+f"(d[2]), "+f"(d[3])
        : "r"(a[0]), "r"(a[1]), "r"(a[2]), "r"(a[3]), "r"(b[0]), "r"(b[1]));
}
__device__ __forceinline__ void mma16(float* d, const uint32_t* a, const uint32_t* b){
    asm volatile("mma.sync.aligned.m16n8k16.row.col.f32.f16.f16.f32 "
        "{%0,%1,%2,%3}, {%4,%5,%6,%7}, {%8,%9}, {%0,%1,%2,%3};"
        : "+f"(d[0]), "+f"(d[1]), "+f"(d[2]), "+f"(d[3])
        : "r"(a[0]), "r"(a[1]), "r"(a[2]), "r"(a[3]), "r"(b[0]), "r"(b[1]));
}
__device__ __forceinline__ uint32_t ldsm(const uint32_t* base, int row, int w){
    return base[row*32 + (w ^ ((row & 7) << 2))];
}
__device__ __forceinline__ uint32_t lds64(const uint32_t* base, int r, int c){
    return base[r*64 + (c ^ ((r & 7) << 2))];
}
__device__ __forceinline__ void cpasync16(uint32_t dst, const void* src){
    asm volatile("cp.async.cg.shared.global [%0], [%1], 16;" :: "r"(dst), "l"(src) : "memory");
}
#define CP_COMMIT() asm volatile("cp.async.commit_group;" ::: "memory")

__device__ __forceinline__ float fexp2n(float y){
    y = fminf(fmaxf(y, -126.f), 126.f);
    float r = y + 12582912.f;
    float f = y - (r - 12582912.f);
    float p = 1.3333558146e-3f;
    p = fmaf(p, f, 9.6181291776e-3f);
    p = fmaf(p, f, 5.5504108664e-2f);
    p = fmaf(p, f, 2.4022650696e-1f);
    p = fmaf(p, f, 6.9314718056e-1f);
    p = fmaf(p, f, 1.0f);
    return __int_as_float(__float_as_int(p) + (__float_as_int(r) << 23));
}
__device__ __forceinline__ float fexps(float s){ return fexp2n(s * 0.18033688011112042f); }
__device__ __forceinline__ float frcp(float x){
    float y = __int_as_float(0x7EF311C3 - __float_as_int(x));
    y = y * (2.f - x*y);
    y = y * (2.f - x*y);
    y = y * (2.f - x*y);
    return y;
}
__device__ __forceinline__ float fsilu(float a){
    float t = fexp2n(-a * 1.4426950408889634f);
    return a * frcp(1.f + t);
}

// ---------------- fp32 -> fp16 conversion ----------------
__global__ void __launch_bounds__(256) cvt_kernel(const float4* __restrict__ src,
                                                  __half2* __restrict__ dst, int n4)
{
    int i = blockIdx.x * 256 + threadIdx.x;
    if (i < n4) {
        float4 v = src[i];
        dst[2*i]   = __floats2half2_rn(v.x, v.y);
        dst[2*i+1] = __floats2half2_rn(v.z, v.w);
    }
}

// ---------------- rmsnorm (WHICH=1: fp16 out + gate logits) ----------------
template<int WHICH>
__global__ void __launch_bounds__(256) rmsnorm_kernel(const float* __restrict__ x,
                                                      const float* __restrict__ w,
                                                      const float* __restrict__ gw)
{
    int n = blockIdx.x;
    int t = threadIdx.x;
    const float* row = (WHICH == 0) ? (x + (size_t)n*DM) : (g_res + (size_t)n*DM);

    float v0 = row[t], v1 = row[t+256], v2 = row[t+512];
    float ss = v0*v0 + v1*v1 + v2*v2;

    __shared__ float red[8];
    __shared__ float part[8][8];
    #pragma unroll
    for (int o = 16; o; o >>= 1) ss += __shfl_down_sync(0xffffffffu, ss, o);
    if ((t & 31) == 0) red[t >> 5] = ss;
    __syncthreads();
    if (t < 8) {
        ss = red[t];
        #pragma unroll
        for (int o = 4; o; o >>= 1) ss += __shfl_down_sync(0xffu, ss, o);
        if (t == 0) red[0] = ss;
    }
    __syncthreads();
    float inv = rsqrtf(red[0] * (1.0f/DM) + 1e-5f);
    float o0 = v0*inv*w[t], o1 = v1*inv*w[t+256], o2 = v2*inv*w[t+512];
    if (WHICH == 0) {
        float* out = g_xn + (size_t)n*DM;
        out[t] = o0; out[t+256] = o1; out[t+512] = o2;
    } else {
        __half* out = g_xf + (size_t)n*DM;
        out[t]     = __float2half_rn(o0);
        out[t+256] = __float2half_rn(o1);
        out[t+512] = __float2half_rn(o2);
        float d[8];
        #pragma unroll
        for (int e = 0; e < 8; e++)
            d[e] = o0*gw[e*DM + t] + o1*gw[e*DM + t + 256] + o2*gw[e*DM + t + 512];
        #pragma unroll
        for (int e = 0; e < 8; e++) {
            #pragma unroll
            for (int o = 16; o; o >>= 1) d[e] += __shfl_down_sync(0xffffffffu, d[e], o);
        }
        if ((t & 31) == 0) {
            #pragma unroll
            for (int e = 0; e < 8; e++) part[t >> 5][e] = d[e];
        }
        __syncthreads();
        if (t < 8) {
            float l = 0.f;
            #pragma unroll
            for (int wv = 0; wv < 8; wv++) l += part[wv][t];
            g_logits[n*NE + t] = l;
        }
    }
}

// ---------------- merged routing ----------------
__global__ void __launch_bounds__(1024) route_kernel()
{
    __shared__ int cnt[NE], off[NE], fill[NE];
    int t = threadIdx.x;
    if (t < NE) { cnt[t] = 0; fill[t] = 0; }
    __syncthreads();

    int eidx[2][2];
    #pragma unroll
    for (int j = 0; j < 2; j++) {
        int n = t*2 + j;
        float lg[NE];
        #pragma unroll
        for (int i = 0; i < NE; i++) lg[i] = g_logits[n*NE + i];
        float m = -1e30f;
        #pragma unroll
        for (int i = 0; i < NE; i++) m = fmaxf(m, lg[i]);
        float s = 0.f;
        #pragma unroll
        for (int i = 0; i < NE; i++) { lg[i] = fexp2n((lg[i] - m) * 1.4426950408889634f); s += lg[i]; }
        float invs = 1.f / s;
        int e0 = -1, e1 = -1; float v0 = -1.f, v1 = -1.f;
        #pragma unroll
        for (int i = 0; i < NE; i++) {
            float v = lg[i] * invs;
            if (v > v0) { v1 = v0; e1 = e0; v0 = v; e0 = i; }
            else if (v > v1) { v1 = v; e1 = i; }
        }
        g_wts[2*n]     = fmaxf(v0, 1e-7f);
        g_wts[2*n + 1] = fmaxf(v1, 1e-7f);
        eidx[j][0] = e0; eidx[j][1] = e1;
        atomicAdd(&cnt[e0], 1);
        atomicAdd(&cnt[e1], 1);
    }
    __syncthreads();
    if (t == 0) {
        int o = 0;
        for (int e = 0; e < NE; e++) { g_counts[e] = cnt[e]; off[e] = o; g_offsets[e] = o; o += cnt[e]; }
    }
    __syncthreads();
    #pragma unroll
    for (int j = 0; j < 2; j++) {
        #pragma unroll
        for (int k = 0; k < 2; k++) {
            int e = eidx[j][k];
            int p = atomicAdd(&fill[e], 1);
            g_list[off[e] + p] = (t*2 + j)*2 + k;
        }
    }
}

// ---------------- attention: tf32 mma + fast exp ----------------
__global__ void __launch_bounds__(256) attn_mma_kernel(const float* __restrict__ x)
{
    int q0 = blockIdx.x * 64;
    int h  = blockIdx.y;

    extern __shared__ __align__(16) uint32_t sm[];
    uint32_t* Qs = sm;
    uint32_t* Ks = sm + 4096;
    uint32_t* Vt = sm + 8192;
    uint32_t* Ps = sm + 12288;
    float* rssm  = (float*)(sm + 16384);

    int tid = threadIdx.x, lane = tid & 31, wid = tid >> 5;
    int wm = wid & 3, wn = wid >> 2, gid = lane >> 2, qid = lane & 3;

    {
        int r = tid >> 2, c4 = (tid & 3) * 16;
        const float* src = g_xn + (size_t)(q0 + r)*DM + h*HD + c4;
        #pragma unroll
        for (int j = 0; j < 4; j++) {
            float4 v = *(const float4*)(src + 4*j);
            uint32_t c = (uint32_t)((c4 + 4*j) ^ ((r & 7) << 2));
            uint4 u = make_uint4(tf32c(v.x), tf32c(v.y), tf32c(v.z), tf32c(v.w));
            *(uint4*)&Qs[r*64 + c] = u;
        }
    }

    float acc_o[4][4] = {};
    float rs0 = 0.f, rs1 = 0.f;
    int r0 = wm*16 + gid;

    for (int kt = 0; kt < SQ/64; kt++) {
        __syncthreads();
        {
            int r = tid >> 2, c4 = (tid & 3) * 16;
            const float* src = g_xn + (size_t)(kt*64 + r)*DM + h*HD + c4;
            #pragma unroll
            for (int j = 0; j < 4; j++) {
                float4 v = *(const float4*)(src + 4*j);
                int d0 = c4 + 4*j;
                uint4 u = make_uint4(tf32c(v.x), tf32c(v.y), tf32c(v.z), tf32c(v.w));
                *(uint4*)&Ks[r*64 + (d0 ^ ((r & 7) << 2))] = u;
                Vt[(d0+0)*64 + (r ^ (((d0+0) & 7) << 2))] = u.x;
                Vt[(d0+1)*64 + (r ^ (((d0+1) & 7) << 2))] = u.y;
                Vt[(d0+2)*64 + (r ^ (((d0+2) & 7) << 2))] = u.z;
                Vt[(d0+3)*64 + (r ^ (((d0+3) & 7) << 2))] = u.w;
            }
        }
        __syncthreads();

        float acc_s[4][4] = {};
        #pragma unroll
        for (int kk = 0; kk < 8; kk++) {
            int kb = kk * 8;
            uint32_t af[4];
            af[0] = lds64(Qs, r0,     kb + qid);
            af[1] = lds64(Qs, r0 + 8, kb + qid);
            af[2] = lds64(Qs, r0,     kb + qid + 4);
            af[3] = lds64(Qs, r0 + 8, kb + qid + 4);
            #pragma unroll
            for (int ni = 0; ni < 4; ni++) {
                uint32_t bf[2];
                int n = wn*32 + 8*ni + gid;
                bf[0] = lds64(Ks, n, kb + qid);
                bf[1] = lds64(Ks, n, kb + qid + 4);
                mma8(acc_s[ni], af, bf);
            }
        }

        float p0 = 0.f, p1 = 0.f;
        #pragma unroll
        for (int ni = 0; ni < 4; ni++) {
            float e0 = fexps(acc_s[ni][0]);
            float e1 = fexps(acc_s[ni][1]);
            float e2 = fexps(acc_s[ni][2]);
            float e3 = fexps(acc_s[ni][3]);
            p0 += e0 + e1;
            p1 += e2 + e3;
            int col = wn*32 + 8*ni + 2*qid;
            uint2 u0 = make_uint2(tf32c(e0), tf32c(e1));
            uint2 u1 = make_uint2(tf32c(e2), tf32c(e3));
            *(uint2*)&Ps[r0*64 + (col ^ ((r0 & 7) << 2))] = u0;
            int r1 = r0 + 8;
            *(uint2*)&Ps[r1*64 + (col ^ ((r1 & 7) << 2))] = u1;
        }
        p0 += __shfl_xor_sync(0xffffffffu, p0, 1);
        p0 += __shfl_xor_sync(0xffffffffu, p0, 2);
        p1 += __shfl_xor_sync(0xffffffffu, p1, 1);
        p1 += __shfl_xor_sync(0xffffffffu, p1, 2);
        rs0 += p0; rs1 += p1;
        __syncthreads();

        #pragma unroll
        for (int kk = 0; kk < 8; kk++) {
            int kb = kk * 8;
            uint32_t af[4];
            af[0] = lds64(Ps, r0,     kb + qid);
            af[1] = lds64(Ps, r0 + 8, kb + qid);
            af[2] = lds64(Ps, r0,     kb + qid + 4);
            af[3] = lds64(Ps, r0 + 8, kb + qid + 4);
            #pragma unroll
            for (int ni = 0; ni < 4; ni++) {
                uint32_t bf[2];
                int n = wn*32 + 8*ni + gid;
                bf[0] = lds64(Vt, n, kb + qid);
                bf[1] = lds64(Vt, n, kb + qid + 4);
                mma8(acc_o[ni], af, bf);
            }
        }
    }

    if (qid == 0) {
        rssm[wn*64 + r0]     = rs0;
        rssm[wn*64 + r0 + 8] = rs1;
    }
    __syncthreads();
    float inv0 = 1.f / (rssm[r0]     + rssm[64 + r0]);
    float inv1 = 1.f / (rssm[r0 + 8] + rssm[64 + r0 + 8]);

    #pragma unroll
    for (int ni = 0; ni < 4; ni++) {
        int col = h*HD + wn*32 + 8*ni + 2*qid;
        size_t gi0 = (size_t)(q0 + r0)*DM + col;
        size_t gi1 = (size_t)(q0 + r0 + 8)*DM + col;
        float2 x0 = *(const float2*)&x[gi0];
        float2 x1 = *(const float2*)&x[gi1];
        float2 o0 = make_float2(x0.x + acc_o[ni][0]*inv0, x0.y + acc_o[ni][1]*inv0);
        float2 o1 = make_float2(x1.x + acc_o[ni][2]*inv1, x1.y + acc_o[ni][3]*inv1);
        *(float2*)&g_res[gi0] = o0;
        *(float2*)&g_res[gi1] = o1;
    }
}

// ---------------- h = silu(a) * g -> fp16 ----------------
__global__ void silu_mul_kernel()
{
    int i = (blockIdx.x * 256 + threadIdx.x) * 4;
    float4 a = *(float4*)&g_a[i];
    float4 g = *(float4*)&g_gv[i];
    __half2 h0 = __floats2half2_rn(fsilu(a.x)*g.x, fsilu(a.y)*g.y);
    __half2 h1 = __floats2half2_rn(fsilu(a.z)*g.z, fsilu(a.w)*g.w);
    *(__half2*)&g_h[i]   = h0;
    *(__half2*)&g_h[i+2] = h1;
}

// ---------------- fp16 mma GEMM, cp.async 3-stage, K-chunk=64, tile BM x 128 ----------------
template<int MODE, int BM>
__global__ void __launch_bounds__(256, 2) mma_gemm(const __half* __restrict__ Bw,
                                                   const __half* __restrict__ Bw2,
                                                   float* __restrict__ Cout,
                                                   const float* __restrict__ bias,
                                                   const float* __restrict__ bias2)
{
    constexpr int KD  = (MODE==1) ? ISH : (MODE==3 ? NI : DM);
    constexpr int NC  = KD / 64;
    constexpr int NN  = (MODE==0) ? ISH : (MODE==2 ? NI : DM);
    constexpr int AW  = BM * 32;
    constexpr int BOFF = 3 * AW;
    constexpr int WMN = (BM==128) ? 4 : 2;
    constexpr int NIT = (BM==128) ? 8 : 4;
    constexpr int WNW = (BM==128) ? 64 : 32;

    int bx = blockIdx.x;
    int tgt = 0;
    const __half* Bsel = Bw;
    const float* bsel = bias;
    if (MODE == 2 && bx >= NI/128) { tgt = 1; bx -= NI/128; Bsel = Bw2; bsel = bias2; }
    int n0 = bx * 128;
    int m0 = blockIdx.y * BM;
    int M = SQ, moff = 0;

    if (MODE >= 2) {
        int e = blockIdx.z;
        int cnt = g_counts[e];
        if (m0 >= cnt) return;
        M = cnt; moff = g_offsets[e];
        Bsel += (size_t)e * NN * KD;
        bsel += (size_t)e * NN;
    }

    extern __shared__ __align__(128) uint32_t smu[];
    uint32_t smbase = smem_u32(smu);

    int tid = threadIdx.x, lane = tid & 31, wid = tid >> 5;
    int wm = wid & (WMN-1), wn = wid / WMN;
    int gid = lane >> 2, qid = lane & 3;

    int ra;
    int hofa[4];
    uint32_t sba[4];
    if (BM == 128) {
        ra = tid >> 1;
        int b0 = (tid & 1) * 64;
        #pragma unroll
        for (int i = 0; i < 4; i++) {
            int bo = b0 + i*16;
            hofa[i] = bo >> 1;
            sba[i] = (uint32_t)(ra*128 + (bo ^ ((ra & 7) << 4)));
        }
    } else {
        ra = tid >> 2;
        int b0 = (tid & 3) * 32;
        #pragma unroll
        for (int i = 0; i < 2; i++) {
            int bo = b0 + i*16;
            hofa[i] = bo >> 1;
            sba[i] = (uint32_t)(ra*128 + (bo ^ ((ra & 7) << 4)));
        }
        hofa[2] = hofa[3] = 0; sba[2] = sba[3] = 0;
    }
    int mrow = m0 + ra; if (mrow > M - 1) mrow = M - 1;
    const __half* arow;
    if      (MODE == 2) arow = g_xf + (size_t)(g_list[moff + mrow] >> 1) * DM;
    else if (MODE == 3) arow = g_h  + (size_t)(moff + mrow) * NI;
    else if (MODE == 1) arow = g_t  + (size_t)mrow * ISH;
    else                arow = g_xf + (size_t)mrow * DM;

    int rb = tid >> 1;
    int bb0 = (tid & 1) * 64;
    const __half* brow = Bsel + (size_t)(n0 + rb) * KD;
    int hofb[4]; uint32_t sbb[4];
    #pragma unroll
    for (int i = 0; i < 4; i++) {
        int bo = bb0 + i*16;
        hofb[i] = bo >> 1;
        sbb[i] = (uint32_t)(rb*128 + (bo ^ ((rb & 7) << 4)));
    }

#define ISSUE_CHUNK(KC) do { \
        int _kc = (KC); \
        int _st = _kc % 3; \
        uint32_t _da = smbase + (uint32_t)(_st * AW * 4); \
        uint32_t _db = smbase + (uint32_t)((BOFF + _st * 4096) * 4); \
        const __half* _as = arow + _kc*64; \
        const __half* _bs = brow + _kc*64; \
        cpasync16(_da + sba[0], _as + hofa[0]); \
        cpasync16(_da + sba[1], _as + hofa[1]); \
        if (BM == 128) { \
            cpasync16(_da + sba[2], _as + hofa[2]); \
            cpasync16(_da + sba[3], _as + hofa[3]); \
        } \
        cpasync16(_db + sbb[0], _bs + hofb[0]); \
        cpasync16(_db + sbb[1], _bs + hofb[1]); \
        cpasync16(_db + sbb[2], _bs + hofb[2]); \
        cpasync16(_db + sbb[3], _bs + hofb[3]); \
        CP_COMMIT(); \
    } while (0)

    ISSUE_CHUNK(0);
    ISSUE_CHUNK(1);

    float acc[2][NIT][4] = {};

    for (int kc = 0; kc < NC; kc++) {
        if (kc == NC - 1) { asm volatile("cp.async.wait_group 0;" ::: "memory"); }
        else              { asm volatile("cp.async.wait_group 1;" ::: "memory"); }
        __syncthreads();
        if (kc + 2 < NC) ISSUE_CHUNK(kc + 2);

        int st = kc % 3;
        const uint32_t* cA = smu + st * AW;
        const uint32_t* cB = smu + BOFF + st * 4096;
        #pragma unroll
        for (int kk = 0; kk < 4; kk++) {
            int kb = kk * 8;
            uint32_t af[2][4], bf[NIT][2];
            #pragma unroll
            for (int mi = 0; mi < 2; mi++) {
                int rr = 32*wm + 16*mi + gid;
                af[mi][0] = ldsm(cA, rr,     kb + qid);
                af[mi][1] = ldsm(cA, rr + 8, kb + qid);
                af[mi][2] = ldsm(cA, rr,     kb + qid + 4);
                af[mi][3] = ldsm(cA, rr + 8, kb + qid + 4);
            }
            #pragma unroll
            for (int ni = 0; ni < NIT; ni++) {
                int n = WNW*wn + 8*ni + gid;
                bf[ni][0] = ldsm(cB, n, kb + qid);
                bf[ni][1] = ldsm(cB, n, kb + qid + 4);
            }
            #pragma unroll
            for (int mi = 0; mi < 2; mi++)
                #pragma unroll
                for (int ni = 0; ni < NIT; ni++)
                    mma16(acc[mi][ni], af[mi], bf[ni]);
        }
    }
#undef ISSUE_CHUNK

    #pragma unroll
    for (int mi = 0; mi < 2; mi++) {
        #pragma unroll
        for (int half = 0; half < 2; half++) {
            int row = m0 + 32*wm + 16*mi + gid + 8*half;
            if (MODE >= 2 && row >= M) continue;
            #pragma unroll
            for (int ni = 0; ni < NIT; ni++) {
                float v0 = acc[mi][ni][2*half + 0];
                float v1 = acc[mi][ni][2*half + 1];
                int col = n0 + WNW*wn + 8*ni + 2*qid;
                float b0 = bsel[col], b1 = bsel[col + 1];
                if (MODE == 0) {
                    *(__half2*)&g_t[(size_t)row*ISH + col] =
                        __floats2half2_rn(fsilu(v0 + b0), fsilu(v1 + b1));
                } else if (MODE == 1) {
                    float2 rr = *(const float2*)&g_res[(size_t)row*DM + col];
                    float2 a0 = *(const float2*)&g_yk[(size_t)(2*row)*DM + col];
                    float2 a1 = *(const float2*)&g_yk[(size_t)(2*row + 1)*DM + col];
                    float2 o  = make_float2(v0 + b0 + rr.x + a0.x + a1.x,
                                            v1 + b1 + rr.y + a0.y + a1.y);
                    *(float2*)&Cout[(size_t)row*DM + col] = o;
                } else if (MODE == 2) {
                    float* dst = (tgt ? g_gv : g_a) + (size_t)(moff + row)*NI + col;
                    *(float2*)dst = make_float2(v0 + b0, v1 + b1);
                } else {
                    int code = g_list[moff + row];
                    float w = g_wts[code];
                    float2 o = make_float2(w*(v0 + b0), w*(v1 + b1));
                    *(float2*)&g_yk[(size_t)code*DM + col] = o;
                }
            }
        }
    }
}

// ---------------- launch ----------------
extern "C" void kernel_launch(void* const* d_in, const int* in_sizes, int n_in,
                              void* d_out, int out_size)
{
    const float* x       = (const float*)d_in[0];
    const float* norm1_w = (const float*)d_in[1];
    const float* norm3_w = (const float*)d_in[2];
    const float* gate_w  = (const float*)d_in[3];
    const float* w1      = (const float*)d_in[4];
    const float* b1      = (const float*)d_in[5];
    const float* w2      = (const float*)d_in[6];
    const float* b2      = (const float*)d_in[7];
    const float* w3      = (const float*)d_in[8];
    const float* b3      = (const float*)d_in[9];
    const float* fc1_w   = (const float*)d_in[10];
    const float* fc1_b   = (const float*)d_in[11];
    const float* fc2_w   = (const float*)d_in[12];
    const float* fc2_b   = (const float*)d_in[13];
    float* out = (float*)d_out;

    const int SMG128 = 98304;
    const int SMG64  = 73728;
    const int SMA    = 16384*4 + 512;

    static cudaStream_t s2 = nullptr;
    static cudaEvent_t evRoot = nullptr, evA = nullptr, evB = nullptr, evC = nullptr;
    static __half *p_w1, *p_w3, *p_w2, *p_fc1, *p_fc2;
    if (!s2) {
        cudaStreamCreateWithFlags(&s2, cudaStreamNonBlocking);
        cudaEventCreateWithFlags(&evRoot, cudaEventDisableTiming);
        cudaEventCreateWithFlags(&evA, cudaEventDisableTiming);
        cudaEventCreateWithFlags(&evB, cudaEventDisableTiming);
        cudaEventCreateWithFlags(&evC, cudaEventDisableTiming);
        cudaFuncSetAttribute((mma_gemm<0,128>), cudaFuncAttributeMaxDynamicSharedMemorySize, SMG128);
        cudaFuncSetAttribute((mma_gemm<1,64>),  cudaFuncAttributeMaxDynamicSharedMemorySize, SMG64);
        cudaFuncSetAttribute((mma_gemm<2,128>), cudaFuncAttributeMaxDynamicSharedMemorySize, SMG128);
        cudaFuncSetAttribute((mma_gemm<3,64>),  cudaFuncAttributeMaxDynamicSharedMemorySize, SMG64);
        cudaFuncSetAttribute(attn_mma_kernel,   cudaFuncAttributeMaxDynamicSharedMemorySize, SMA);
        cudaGetSymbolAddress((void**)&p_w1,  h_w1);
        cudaGetSymbolAddress((void**)&p_w3,  h_w3);
        cudaGetSymbolAddress((void**)&p_w2,  h_w2);
        cudaGetSymbolAddress((void**)&p_fc1, h_fc1);
        cudaGetSymbolAddress((void**)&p_fc2, h_fc2);
    }

    // fork s2 FROM THE CAPTURE STREAM first (capture-legal), then enqueue
    // weight conversions on s2, overlapped with rmsnorm + attention on stream 0.
    cudaEventRecord(evRoot, 0);
    cudaStreamWaitEvent(s2, evRoot, 0);
    cvt_kernel<<<(NE*NI*DM/4+255)/256, 256, 0, s2>>>((const float4*)w1,    (__half2*)p_w1,  NE*NI*DM/4);
    cvt_kernel<<<(NE*NI*DM/4+255)/256, 256, 0, s2>>>((const float4*)w3,    (__half2*)p_w3,  NE*NI*DM/4);
    cvt_kernel<<<(NE*DM*NI/4+255)/256, 256, 0, s2>>>((const float4*)w2,    (__half2*)p_w2,  NE*DM*NI/4);
    cvt_kernel<<<(ISH*DM/4+255)/256,   256, 0, s2>>>((const float4*)fc1_w, (__half2*)p_fc1, ISH*DM/4);
    cvt_kernel<<<(DM*ISH/4+255)/256,   256, 0, s2>>>((const float4*)fc2_w, (__half2*)p_fc2, DM*ISH/4);
    cudaEventRecord(evC, s2);

    rmsnorm_kernel<0><<<SQ, 256>>>(x, norm1_w, nullptr);
    attn_mma_kernel<<<dim3(SQ/64, NH), 256, SMA>>>(x);
    rmsnorm_kernel<1><<<SQ, 256>>>(nullptr, norm3_w, gate_w);

    // fork fc1 on s2 (after g_xf ready; conversions already ordered on s2)
    cudaEventRecord(evA, 0);
    cudaStreamWaitEvent(s2, evA, 0);
    mma_gemm<0,128><<<dim3(ISH/128, SQ/128), 256, SMG128, s2>>>(p_fc1, nullptr, nullptr, fc1_b, nullptr);
    cudaEventRecord(evB, s2);

    route_kernel<<<1, 1024>>>();
    cudaStreamWaitEvent(0, evC, 0);
    mma_gemm<2,128><<<dim3(2*NI/128, 32, NE), 256, SMG128>>>(p_w1, p_w3, nullptr, b1, b3);
    silu_mul_kernel<<<(NSLOT*NI)/1024, 256>>>();
    mma_gemm<3,64><<<dim3(DM/128, NSLOT/64, NE), 256, SMG64>>>(p_w2, nullptr, nullptr, b2, nullptr);

    cudaStreamWaitEvent(0, evB, 0);
    mma_gemm<1,64><<<dim3(DM/128, SQ/64), 256, SMG64>>>(p_fc2, nullptr, out, fc2_b, nullptr);
}